// round 1
// baseline (speedup 1.0000x reference)
#include <cuda_runtime.h>
#include <math.h>

// Problem constants
#define BB   4
#define SS   2048
#define DD   1024
#define HH   16
#define DHH  64
#define FFD  4096
#define MM   (BB*SS)      // 8192 rows

// ---------------------------------------------------------------------------
// Scratch (static __device__ — no allocations allowed)
// ---------------------------------------------------------------------------
__device__ float g_ln [MM*DD];        // reused for ln_attn out and ln2 out
__device__ float g_qkv[MM*3*DD];
__device__ float g_att[MM*DD];
__device__ float g_ctx[MM*DD];
__device__ float g_x1 [MM*DD];
__device__ float g_xs [MM*DD];
__device__ float g_u  [MM*DD];
__device__ float g_al [MM*DD];
__device__ float g_be [MM*DD];
__device__ float g_gg [MM*DD];
__device__ float g_x2 [MM*DD];
__device__ float g_ff [MM*FFD];

// ---------------------------------------------------------------------------
// LayerNorm: one block per row (D=1024, 256 threads, 4 floats/thread)
// ---------------------------------------------------------------------------
__global__ void __launch_bounds__(256) ln_kernel(
    const float* __restrict__ x, const float* __restrict__ w,
    const float* __restrict__ b, float* __restrict__ out)
{
    int row = blockIdx.x;
    int tid = threadIdx.x;
    const float4* xr = (const float4*)(x + (size_t)row * DD);
    float4 v = xr[tid];

    __shared__ float red[8];
    // mean
    float s = v.x + v.y + v.z + v.w;
    #pragma unroll
    for (int o = 16; o > 0; o >>= 1) s += __shfl_xor_sync(0xffffffffu, s, o);
    if ((tid & 31) == 0) red[tid >> 5] = s;
    __syncthreads();
    __shared__ float s_mean, s_rstd;
    if (tid == 0) {
        float t = 0.f;
        #pragma unroll
        for (int i = 0; i < 8; i++) t += red[i];
        s_mean = t * (1.0f / DD);
    }
    __syncthreads();
    float mean = s_mean;
    float d0 = v.x - mean, d1 = v.y - mean, d2 = v.z - mean, d3 = v.w - mean;
    // variance
    float sq = d0*d0 + d1*d1 + d2*d2 + d3*d3;
    #pragma unroll
    for (int o = 16; o > 0; o >>= 1) sq += __shfl_xor_sync(0xffffffffu, sq, o);
    __syncthreads();
    if ((tid & 31) == 0) red[tid >> 5] = sq;
    __syncthreads();
    if (tid == 0) {
        float t = 0.f;
        #pragma unroll
        for (int i = 0; i < 8; i++) t += red[i];
        s_rstd = rsqrtf(t * (1.0f / DD) + 1e-5f);
    }
    __syncthreads();
    float rstd = s_rstd;
    float4 wv = ((const float4*)w)[tid];
    float4 bv = ((const float4*)b)[tid];
    float4 o4;
    o4.x = d0 * rstd * wv.x + bv.x;
    o4.y = d1 * rstd * wv.y + bv.y;
    o4.z = d2 * rstd * wv.z + bv.z;
    o4.w = d3 * rstd * wv.w + bv.w;
    ((float4*)(out + (size_t)row * DD))[tid] = o4;
}

// ---------------------------------------------------------------------------
// NT SGEMM: C[M,N] = A[M,K] @ W[N,K]^T + bias, templated epilogue.
// 128x128 block tile, 16 K-tile, 256 threads, 8x8 per-thread microtile.
// EPI: 0=none 1=gelu 2=sigmoid 3=softplus 4=C=v+res 5=dual(C=v, C2=v+res)
// ---------------------------------------------------------------------------
template<int EPI>
__global__ void __launch_bounds__(256, 2) gemm_nt(
    const float* __restrict__ A, const float* __restrict__ W,
    const float* __restrict__ bias, float* __restrict__ C,
    float* __restrict__ C2, const float* __restrict__ res,
    int M, int N, int K)
{
    __shared__ float As[16][132];
    __shared__ float Bs[16][132];

    int tid = threadIdx.x;
    int tx = tid & 15, ty = tid >> 4;
    int rowC = blockIdx.y * 128 + ty * 8;
    int colC = blockIdx.x * 128 + tx * 8;

    int lrow = tid >> 2;            // 0..63
    int lk   = (tid & 3) * 4;       // 0,4,8,12
    const float* Ap = A + (size_t)(blockIdx.y * 128 + lrow) * K + lk;
    const float* Wp = W + (size_t)(blockIdx.x * 128 + lrow) * K + lk;

    float acc[8][8];
    #pragma unroll
    for (int i = 0; i < 8; i++)
        #pragma unroll
        for (int j = 0; j < 8; j++) acc[i][j] = 0.f;

    for (int kt = 0; kt < K; kt += 16) {
        float4 a0 = *(const float4*)(Ap + kt);
        float4 a1 = *(const float4*)(Ap + (size_t)64 * K + kt);
        float4 b0 = *(const float4*)(Wp + kt);
        float4 b1 = *(const float4*)(Wp + (size_t)64 * K + kt);
        __syncthreads();
        As[lk+0][lrow] = a0.x; As[lk+1][lrow] = a0.y; As[lk+2][lrow] = a0.z; As[lk+3][lrow] = a0.w;
        As[lk+0][lrow+64] = a1.x; As[lk+1][lrow+64] = a1.y; As[lk+2][lrow+64] = a1.z; As[lk+3][lrow+64] = a1.w;
        Bs[lk+0][lrow] = b0.x; Bs[lk+1][lrow] = b0.y; Bs[lk+2][lrow] = b0.z; Bs[lk+3][lrow] = b0.w;
        Bs[lk+0][lrow+64] = b1.x; Bs[lk+1][lrow+64] = b1.y; Bs[lk+2][lrow+64] = b1.z; Bs[lk+3][lrow+64] = b1.w;
        __syncthreads();
        #pragma unroll
        for (int k = 0; k < 16; k++) {
            float4 af0 = *(const float4*)&As[k][ty * 8];
            float4 af1 = *(const float4*)&As[k][ty * 8 + 4];
            float4 bf0 = *(const float4*)&Bs[k][tx * 8];
            float4 bf1 = *(const float4*)&Bs[k][tx * 8 + 4];
            float a_[8] = {af0.x, af0.y, af0.z, af0.w, af1.x, af1.y, af1.z, af1.w};
            float b_[8] = {bf0.x, bf0.y, bf0.z, bf0.w, bf1.x, bf1.y, bf1.z, bf1.w};
            #pragma unroll
            for (int i = 0; i < 8; i++)
                #pragma unroll
                for (int j = 0; j < 8; j++)
                    acc[i][j] = fmaf(a_[i], b_[j], acc[i][j]);
        }
    }

    #pragma unroll
    for (int i = 0; i < 8; i++) {
        size_t rbase = (size_t)(rowC + i) * N + colC;
        #pragma unroll
        for (int j = 0; j < 8; j++) {
            float v = acc[i][j] + bias[colC + j];
            if (EPI == 1) v = 0.5f * v * (1.0f + erff(v * 0.70710678118654752f));
            else if (EPI == 2) v = 1.0f / (1.0f + expf(-v));
            else if (EPI == 3) v = (v > 0.f) ? (v + log1pf(expf(-v))) : log1pf(expf(v));
            if (EPI == 4)      C[rbase + j] = v + res[rbase + j];
            else if (EPI == 5) { C[rbase + j] = v; C2[rbase + j] = v + res[rbase + j]; }
            else               C[rbase + j] = v;
        }
    }
}

// ---------------------------------------------------------------------------
// Causal flash attention, fp32. Q tile 64, KV tile 32, dh=64.
// grid: (S/64, B*H); 256 threads. Static shared < 48KB.
// qkv layout [B,S,3D]; out layout [B,S,D] (heads concatenated).
// ---------------------------------------------------------------------------
__global__ void __launch_bounds__(256) attn_kernel(
    const float* __restrict__ qkv, float* __restrict__ out)
{
    __shared__ float Qs[64][68];
    __shared__ float Ks[32][68];
    __shared__ float Vs[32][68];
    __shared__ float Ss[64][36];
    __shared__ float m_s[64], l_s[64], rs_s[64];

    int tid = threadIdx.x;
    int bh = blockIdx.y;
    int b = bh / HH, h = bh % HH;
    int q0 = blockIdx.x * 64;
    const float scale = 0.125f;  // 1/sqrt(64)

    // Load Q tile: 64 rows x 64 cols
    #pragma unroll
    for (int i = 0; i < 4; i++) {
        int f = tid + i * 256;
        int r = f >> 4;
        int c = (f & 15) * 4;
        *(float4*)&Qs[r][c] =
            *(const float4*)&qkv[(size_t)(b * SS + q0 + r) * (3 * DD) + h * DHH + c];
    }
    if (tid < 64) { m_s[tid] = -1e30f; l_s[tid] = 0.f; rs_s[tid] = 0.f; }

    int orow = (tid >> 4) * 4;
    int ocol = (tid & 15) * 4;
    float o[4][4];
    #pragma unroll
    for (int i = 0; i < 4; i++)
        #pragma unroll
        for (int j = 0; j < 4; j++) o[i][j] = 0.f;
    __syncthreads();

    int ntile = 2 * blockIdx.x + 2;   // causal: keys up to q0+63
    for (int j = 0; j < ntile; j++) {
        int k0 = j * 32;
        // Load K,V tiles: 32 x 64 each
        #pragma unroll
        for (int i = 0; i < 2; i++) {
            int f = tid + i * 256;
            int r = f >> 4;
            int c = (f & 15) * 4;
            size_t base = (size_t)(b * SS + k0 + r) * (3 * DD) + h * DHH + c;
            *(float4*)&Ks[r][c] = *(const float4*)&qkv[base + DD];
            *(float4*)&Vs[r][c] = *(const float4*)&qkv[base + 2 * DD];
        }
        __syncthreads();

        // S = Q @ K^T : each thread computes 2 rows x 4 cols
        {
            int sr = (tid >> 3) * 2;
            int sc = (tid & 7) * 4;
            float s0[4] = {0.f, 0.f, 0.f, 0.f};
            float s1[4] = {0.f, 0.f, 0.f, 0.f};
            #pragma unroll
            for (int k4 = 0; k4 < 16; k4++) {
                float4 qa = *(const float4*)&Qs[sr][k4 * 4];
                float4 qb = *(const float4*)&Qs[sr + 1][k4 * 4];
                #pragma unroll
                for (int cc = 0; cc < 4; cc++) {
                    float4 kv = *(const float4*)&Ks[sc + cc][k4 * 4];
                    s0[cc] = fmaf(qa.x, kv.x, fmaf(qa.y, kv.y, fmaf(qa.z, kv.z, fmaf(qa.w, kv.w, s0[cc]))));
                    s1[cc] = fmaf(qb.x, kv.x, fmaf(qb.y, kv.y, fmaf(qb.z, kv.z, fmaf(qb.w, kv.w, s1[cc]))));
                }
            }
            int qg0 = q0 + sr, qg1 = q0 + sr + 1;
            #pragma unroll
            for (int cc = 0; cc < 4; cc++) {
                int kg = k0 + sc + cc;
                Ss[sr][sc + cc]     = (kg > qg0) ? -1e30f : s0[cc] * scale;
                Ss[sr + 1][sc + cc] = (kg > qg1) ? -1e30f : s1[cc] * scale;
            }
        }
        __syncthreads();

        // Online softmax: 4 threads per row, 8 cols each
        {
            int r = tid >> 2;
            int part = tid & 3;
            float mx = -1e30f;
            #pragma unroll
            for (int c = 0; c < 8; c++) mx = fmaxf(mx, Ss[r][part * 8 + c]);
            mx = fmaxf(mx, __shfl_xor_sync(0xffffffffu, mx, 1));
            mx = fmaxf(mx, __shfl_xor_sync(0xffffffffu, mx, 2));
            float mold = m_s[r];
            float mnew = fmaxf(mold, mx);
            float sum = 0.f;
            #pragma unroll
            for (int c = 0; c < 8; c++) {
                float p = expf(Ss[r][part * 8 + c] - mnew);
                Ss[r][part * 8 + c] = p;
                sum += p;
            }
            sum += __shfl_xor_sync(0xffffffffu, sum, 1);
            sum += __shfl_xor_sync(0xffffffffu, sum, 2);
            if (part == 0) {
                float rs = expf(mold - mnew);
                l_s[r] = l_s[r] * rs + sum;
                m_s[r] = mnew;
                rs_s[r] = rs;
            }
        }
        __syncthreads();

        // O = O*rescale + P @ V : each thread 4 rows x 4 cols
        #pragma unroll
        for (int i = 0; i < 4; i++) {
            int r = orow + i;
            float rs = rs_s[r];
            o[i][0] *= rs; o[i][1] *= rs; o[i][2] *= rs; o[i][3] *= rs;
            #pragma unroll
            for (int k = 0; k < 32; k++) {
                float p = Ss[r][k];
                float4 vv = *(const float4*)&Vs[k][ocol];
                o[i][0] = fmaf(p, vv.x, o[i][0]);
                o[i][1] = fmaf(p, vv.y, o[i][1]);
                o[i][2] = fmaf(p, vv.z, o[i][2]);
                o[i][3] = fmaf(p, vv.w, o[i][3]);
            }
        }
        __syncthreads();
    }

    #pragma unroll
    for (int i = 0; i < 4; i++) {
        int r = orow + i;
        float inv = 1.0f / l_s[r];
        float4 ov = make_float4(o[i][0] * inv, o[i][1] * inv, o[i][2] * inv, o[i][3] * inv);
        *(float4*)&out[(size_t)(b * SS + q0 + r) * DD + h * DHH + ocol] = ov;
    }
}

// ---------------------------------------------------------------------------
// INL integrator: purely elementwise, 5 unrolled steps (DT=0.1, TARGET=0).
// alpha/beta/g already activated in GEMM epilogues.
// x2 = x1 + xs_final
// ---------------------------------------------------------------------------
__global__ void __launch_bounds__(256) integrate_kernel(
    const float* __restrict__ xs0, const float* __restrict__ u,
    const float* __restrict__ al, const float* __restrict__ be,
    const float* __restrict__ gg, const float* __restrict__ x1,
    float* __restrict__ x2)
{
    int i = blockIdx.x * blockDim.x + threadIdx.x;
    float4 xs = ((const float4*)xs0)[i];
    float4 uu = ((const float4*)u)[i];
    float4 aa = ((const float4*)al)[i];
    float4 bb = ((const float4*)be)[i];
    float4 g4 = ((const float4*)gg)[i];
    float4 r1 = ((const float4*)x1)[i];
    float4 vs = make_float4(0.f, 0.f, 0.f, 0.f);
    const float DT = 0.1f;
    #pragma unroll
    for (int t = 0; t < 5; t++) {
        vs.x += DT * (-aa.x * xs.x - bb.x * vs.x + uu.x);  xs.x += DT * g4.x * vs.x;
        vs.y += DT * (-aa.y * xs.y - bb.y * vs.y + uu.y);  xs.y += DT * g4.y * vs.y;
        vs.z += DT * (-aa.z * xs.z - bb.z * vs.z + uu.z);  xs.z += DT * g4.z * vs.z;
        vs.w += DT * (-aa.w * xs.w - bb.w * vs.w + uu.w);  xs.w += DT * g4.w * vs.w;
    }
    float4 o4 = make_float4(r1.x + xs.x, r1.y + xs.y, r1.z + xs.z, r1.w + xs.w);
    ((float4*)x2)[i] = o4;
}

// ---------------------------------------------------------------------------
// Host launcher
// ---------------------------------------------------------------------------
extern "C" void kernel_launch(void* const* d_in, const int* in_sizes, int n_in,
                              void* d_out, int out_size)
{
    const float* x          = (const float*)d_in[0];
    const float* ln_attn_w  = (const float*)d_in[1];
    const float* ln_attn_b  = (const float*)d_in[2];
    const float* attn_in_w  = (const float*)d_in[3];
    const float* attn_in_b  = (const float*)d_in[4];
    const float* attn_out_w = (const float*)d_in[5];
    const float* attn_out_b = (const float*)d_in[6];
    const float* ln1_w      = (const float*)d_in[7];
    const float* ln1_b      = (const float*)d_in[8];
    const float* ln2_w      = (const float*)d_in[9];
    const float* ln2_b      = (const float*)d_in[10];
    const float* inl_u_w    = (const float*)d_in[11];
    const float* inl_u_b    = (const float*)d_in[12];
    const float* inl_a_w    = (const float*)d_in[13];
    const float* inl_a_b    = (const float*)d_in[14];
    const float* inl_b_w    = (const float*)d_in[15];
    const float* inl_b_b    = (const float*)d_in[16];
    const float* inl_g_w    = (const float*)d_in[17];
    const float* inl_g_b    = (const float*)d_in[18];
    const float* ff1_w      = (const float*)d_in[19];
    const float* ff1_b      = (const float*)d_in[20];
    const float* ff2_w      = (const float*)d_in[21];
    const float* ff2_b      = (const float*)d_in[22];
    float* out = (float*)d_out;

    float *p_ln, *p_qkv, *p_att, *p_ctx, *p_x1, *p_xs, *p_u, *p_al, *p_be, *p_gg, *p_x2, *p_ff;
    cudaGetSymbolAddress((void**)&p_ln,  g_ln);
    cudaGetSymbolAddress((void**)&p_qkv, g_qkv);
    cudaGetSymbolAddress((void**)&p_att, g_att);
    cudaGetSymbolAddress((void**)&p_ctx, g_ctx);
    cudaGetSymbolAddress((void**)&p_x1,  g_x1);
    cudaGetSymbolAddress((void**)&p_xs,  g_xs);
    cudaGetSymbolAddress((void**)&p_u,   g_u);
    cudaGetSymbolAddress((void**)&p_al,  g_al);
    cudaGetSymbolAddress((void**)&p_be,  g_be);
    cudaGetSymbolAddress((void**)&p_gg,  g_gg);
    cudaGetSymbolAddress((void**)&p_x2,  g_x2);
    cudaGetSymbolAddress((void**)&p_ff,  g_ff);

    // 1. ln_attn(x) -> g_ln
    ln_kernel<<<MM, 256>>>(x, ln_attn_w, ln_attn_b, p_ln);
    // 2. qkv = g_ln @ attn_in_w^T + b   [8192,3072]
    gemm_nt<0><<<dim3(3 * DD / 128, MM / 128), 256>>>(
        p_ln, attn_in_w, attn_in_b, p_qkv, nullptr, nullptr, MM, 3 * DD, DD);
    // 3. causal MHA -> g_att
    attn_kernel<<<dim3(SS / 64, BB * HH), 256>>>(p_qkv, p_att);
    // 4. ctx = g_att @ attn_out_w^T + b ; x1 = x + ctx
    gemm_nt<5><<<dim3(DD / 128, MM / 128), 256>>>(
        p_att, attn_out_w, attn_out_b, p_ctx, p_x1, x, MM, DD, DD);
    // 5. xs = ln1(x1)
    ln_kernel<<<MM, 256>>>(p_x1, ln1_w, ln1_b, p_xs);
    // 6. INL controllers from ctx
    gemm_nt<0><<<dim3(DD / 128, MM / 128), 256>>>(
        p_ctx, inl_u_w, inl_u_b, p_u, nullptr, nullptr, MM, DD, DD);
    gemm_nt<2><<<dim3(DD / 128, MM / 128), 256>>>(
        p_ctx, inl_a_w, inl_a_b, p_al, nullptr, nullptr, MM, DD, DD);
    gemm_nt<3><<<dim3(DD / 128, MM / 128), 256>>>(
        p_ctx, inl_b_w, inl_b_b, p_be, nullptr, nullptr, MM, DD, DD);
    gemm_nt<2><<<dim3(DD / 128, MM / 128), 256>>>(
        p_ctx, inl_g_w, inl_g_b, p_gg, nullptr, nullptr, MM, DD, DD);
    // 7. integrate -> x2 = x1 + xs_final
    integrate_kernel<<<(MM * DD / 4) / 256, 256>>>(p_xs, p_u, p_al, p_be, p_gg, p_x1, p_x2);
    // 8. ln2(x2) -> g_ln
    ln_kernel<<<MM, 256>>>(p_x2, ln2_w, ln2_b, p_ln);
    // 9. ff1 + exact GELU -> g_ff   [8192,4096]
    gemm_nt<1><<<dim3(FFD / 128, MM / 128), 256>>>(
        p_ln, ff1_w, ff1_b, p_ff, nullptr, nullptr, MM, FFD, DD);
    // 10. out = g_ff @ ff2_w^T + b + x2
    gemm_nt<4><<<dim3(DD / 128, MM / 128), 256>>>(
        p_ff, ff2_w, ff2_b, out, nullptr, p_x2, MM, DD, FFD);
}

// round 4
// speedup vs baseline: 1.7541x; 1.7541x over previous
#include <cuda_runtime.h>
#include <cstdint>
#include <math.h>

// Problem constants
#define BB   4
#define SS   2048
#define DD   1024
#define HH   16
#define DHH  64
#define FFD  4096
#define MM   (BB*SS)      // 8192 rows

// ---------------------------------------------------------------------------
// Scratch (static __device__ — no allocations allowed)
// ---------------------------------------------------------------------------
__device__ float g_ln [MM*DD];
__device__ float g_qkv[MM*3*DD];
__device__ float g_att[MM*DD];
__device__ float g_ctx[MM*DD];
__device__ float g_x1 [MM*DD];
__device__ float g_xs [MM*DD];
__device__ float g_u  [MM*DD];
__device__ float g_al [MM*DD];
__device__ float g_be [MM*DD];
__device__ float g_gg [MM*DD];
__device__ float g_x2 [MM*DD];
__device__ float g_ff [MM*FFD];

// ---------------------------------------------------------------------------
// Helpers
// ---------------------------------------------------------------------------
__device__ __forceinline__ uint32_t smem_u32(const void* p) {
    uint32_t a;
    asm("{ .reg .u64 t; cvta.to.shared.u64 t, %1; cvt.u32.u64 %0, t; }" : "=r"(a) : "l"(p));
    return a;
}
__device__ __forceinline__ uint32_t f2tf32(float f) {
    uint32_t u;
    asm("cvt.rna.tf32.f32 %0, %1;" : "=r"(u) : "f"(f));
    return u;
}
__device__ __forceinline__ uint32_t lds_u32(uint32_t addr) {
    uint32_t v;
    asm volatile("ld.shared.b32 %0, [%1];" : "=r"(v) : "r"(addr));
    return v;
}
__device__ __forceinline__ void sts_u4(uint32_t addr, uint32_t x, uint32_t y, uint32_t z, uint32_t w) {
    asm volatile("st.shared.v4.b32 [%0], {%1,%2,%3,%4};" :: "r"(addr), "r"(x), "r"(y), "r"(z), "r"(w));
}
#define SWZ128(off) ((off) ^ (((off) >> 3) & 0x70))

__device__ __forceinline__ void mma_tf32(float* c, const uint32_t* a, uint32_t b0, uint32_t b1) {
    asm volatile("mma.sync.aligned.m16n8k8.row.col.f32.tf32.tf32.f32 "
        "{%0,%1,%2,%3}, {%4,%5,%6,%7}, {%8,%9}, {%0,%1,%2,%3};"
        : "+f"(c[0]), "+f"(c[1]), "+f"(c[2]), "+f"(c[3])
        : "r"(a[0]), "r"(a[1]), "r"(a[2]), "r"(a[3]), "r"(b0), "r"(b1));
}

// ---------------------------------------------------------------------------
// tf32 tensor GEMM: C[M,N] = A[M,K] @ W[N,K]^T + bias (+ epilogue)
// CTA tile 128x128, 256 threads = 8 warps (4M x 2N), warp tile 32x64.
// K-chunk 32, double-buffered SW128-swizzled smem (2 x 32KB).
// EPI: 0=none 1=gelu 2=sigmoid 3=softplus 4=C=v+res 5=dual(C=v, C2=v+res)
// ---------------------------------------------------------------------------
#define STAGE_BYTES 32768   // A tile 16KB + B tile 16KB
#define GEMM_SMEM   (2 * STAGE_BYTES + 1024)

template<int EPI>
__global__ void __launch_bounds__(256, 2) gemm_tc(
    const float* __restrict__ A, const float* __restrict__ W,
    const float* __restrict__ bias, float* __restrict__ C,
    float* __restrict__ C2, const float* __restrict__ res,
    int M, int N, int K)
{
    extern __shared__ char dsm[];
    uint32_t raw = smem_u32(dsm);
    uint32_t base = (raw + 1023u) & ~1023u;

    int tid = threadIdx.x;
    int wid = tid >> 5, lane = tid & 31;
    int gID = lane >> 2, tig = lane & 3;
    int wm = (wid & 3) * 32;       // warp M offset within tile
    int wn = (wid >> 2) * 64;      // warp N offset within tile

    // Global load mapping: thread handles float4 f = tid + i*256, i<4, for A and B.
    // row = f>>3 (0..127), col4 = f&7 (each row = 32 floats = 8 float4).
    int rowL[4], colL[4];
    uint32_t stsOff[4];
    #pragma unroll
    for (int i = 0; i < 4; i++) {
        int f = tid + i * 256;
        rowL[i] = f >> 3;
        colL[i] = (f & 7) * 4;
        stsOff[i] = SWZ128((uint32_t)(rowL[i] * 128 + colL[i] * 4));
    }
    const float* Abase = A + (size_t)(blockIdx.y * 128) * K;
    const float* Wbase = W + (size_t)(blockIdx.x * 128) * K;

    float acc[2][8][4];
    #pragma unroll
    for (int mi = 0; mi < 2; mi++)
        #pragma unroll
        for (int ni = 0; ni < 8; ni++)
            #pragma unroll
            for (int j = 0; j < 4; j++) acc[mi][ni][j] = 0.f;

    const int niter = K / 32;
    float4 ra[4], rb[4];

    // Preload chunk 0
    #pragma unroll
    for (int i = 0; i < 4; i++) {
        ra[i] = *(const float4*)(Abase + (size_t)rowL[i] * K + colL[i]);
        rb[i] = *(const float4*)(Wbase + (size_t)rowL[i] * K + colL[i]);
    }
    #pragma unroll
    for (int i = 0; i < 4; i++) {
        sts_u4(base + stsOff[i], f2tf32(ra[i].x), f2tf32(ra[i].y), f2tf32(ra[i].z), f2tf32(ra[i].w));
        sts_u4(base + 16384 + stsOff[i], f2tf32(rb[i].x), f2tf32(rb[i].y), f2tf32(rb[i].z), f2tf32(rb[i].w));
    }
    __syncthreads();

    for (int it = 0; it < niter; it++) {
        int st = it & 1;
        uint32_t sA = base + st * STAGE_BYTES;
        uint32_t sB = sA + 16384;

        if (it + 1 < niter) {
            int kt = (it + 1) * 32;
            #pragma unroll
            for (int i = 0; i < 4; i++) {
                ra[i] = *(const float4*)(Abase + (size_t)rowL[i] * K + kt + colL[i]);
                rb[i] = *(const float4*)(Wbase + (size_t)rowL[i] * K + kt + colL[i]);
            }
        }

        // Compute on current stage: 4 k8 steps
        #pragma unroll
        for (int s = 0; s < 4; s++) {
            int cb = s * 32 + tig * 4;   // column byte offset for this k-step
            uint32_t afr[2][4];
            #pragma unroll
            for (int mi = 0; mi < 2; mi++) {
                int r = wm + mi * 16 + gID;
                afr[mi][0] = lds_u32(sA + SWZ128((uint32_t)(r * 128 + cb)));
                afr[mi][1] = lds_u32(sA + SWZ128((uint32_t)((r + 8) * 128 + cb)));
                afr[mi][2] = lds_u32(sA + SWZ128((uint32_t)(r * 128 + cb + 16)));
                afr[mi][3] = lds_u32(sA + SWZ128((uint32_t)((r + 8) * 128 + cb + 16)));
            }
            #pragma unroll
            for (int ni = 0; ni < 8; ni++) {
                int n = wn + ni * 8 + gID;
                uint32_t b0 = lds_u32(sB + SWZ128((uint32_t)(n * 128 + cb)));
                uint32_t b1 = lds_u32(sB + SWZ128((uint32_t)(n * 128 + cb + 16)));
                mma_tf32(acc[0][ni], afr[0], b0, b1);
                mma_tf32(acc[1][ni], afr[1], b0, b1);
            }
        }
        __syncthreads();

        if (it + 1 < niter) {
            uint32_t dA = base + (st ^ 1) * STAGE_BYTES;
            #pragma unroll
            for (int i = 0; i < 4; i++) {
                sts_u4(dA + stsOff[i], f2tf32(ra[i].x), f2tf32(ra[i].y), f2tf32(ra[i].z), f2tf32(ra[i].w));
                sts_u4(dA + 16384 + stsOff[i], f2tf32(rb[i].x), f2tf32(rb[i].y), f2tf32(rb[i].z), f2tf32(rb[i].w));
            }
            __syncthreads();
        }
    }

    // Epilogue: c0,c1 at (row = wm+mi*16+gID, col = wn+ni*8+2*tig); c2,c3 at row+8.
    int row0 = blockIdx.y * 128 + wm + gID;
    int col0 = blockIdx.x * 128 + wn;
    #pragma unroll
    for (int mi = 0; mi < 2; mi++) {
        #pragma unroll
        for (int half = 0; half < 2; half++) {
            int r = row0 + mi * 16 + half * 8;
            size_t rbase = (size_t)r * N;
            #pragma unroll
            for (int ni = 0; ni < 8; ni++) {
                int c = col0 + ni * 8 + 2 * tig;
                float v0 = acc[mi][ni][half * 2 + 0] + bias[c];
                float v1 = acc[mi][ni][half * 2 + 1] + bias[c + 1];
                if (EPI == 1) {
                    v0 = 0.5f * v0 * (1.0f + erff(v0 * 0.70710678118654752f));
                    v1 = 0.5f * v1 * (1.0f + erff(v1 * 0.70710678118654752f));
                } else if (EPI == 2) {
                    v0 = 1.0f / (1.0f + expf(-v0));
                    v1 = 1.0f / (1.0f + expf(-v1));
                } else if (EPI == 3) {
                    v0 = (v0 > 0.f) ? (v0 + log1pf(expf(-v0))) : log1pf(expf(v0));
                    v1 = (v1 > 0.f) ? (v1 + log1pf(expf(-v1))) : log1pf(expf(v1));
                }
                if (EPI == 4) {
                    float2 r2 = *(const float2*)(res + rbase + c);
                    *(float2*)(C + rbase + c) = make_float2(v0 + r2.x, v1 + r2.y);
                } else if (EPI == 5) {
                    float2 r2 = *(const float2*)(res + rbase + c);
                    *(float2*)(C + rbase + c)  = make_float2(v0, v1);
                    *(float2*)(C2 + rbase + c) = make_float2(v0 + r2.x, v1 + r2.y);
                } else {
                    *(float2*)(C + rbase + c) = make_float2(v0, v1);
                }
            }
        }
    }
}

// ---------------------------------------------------------------------------
// LayerNorm: one block per row (D=1024, 256 threads, 4 floats/thread)
// ---------------------------------------------------------------------------
__global__ void __launch_bounds__(256) ln_kernel(
    const float* __restrict__ x, const float* __restrict__ w,
    const float* __restrict__ b, float* __restrict__ out)
{
    int row = blockIdx.x;
    int tid = threadIdx.x;
    const float4* xr = (const float4*)(x + (size_t)row * DD);
    float4 v = xr[tid];

    __shared__ float red[8];
    float s = v.x + v.y + v.z + v.w;
    #pragma unroll
    for (int o = 16; o > 0; o >>= 1) s += __shfl_xor_sync(0xffffffffu, s, o);
    if ((tid & 31) == 0) red[tid >> 5] = s;
    __syncthreads();
    __shared__ float s_mean, s_rstd;
    if (tid == 0) {
        float t = 0.f;
        #pragma unroll
        for (int i = 0; i < 8; i++) t += red[i];
        s_mean = t * (1.0f / DD);
    }
    __syncthreads();
    float mean = s_mean;
    float d0 = v.x - mean, d1 = v.y - mean, d2 = v.z - mean, d3 = v.w - mean;
    float sq = d0*d0 + d1*d1 + d2*d2 + d3*d3;
    #pragma unroll
    for (int o = 16; o > 0; o >>= 1) sq += __shfl_xor_sync(0xffffffffu, sq, o);
    __syncthreads();
    if ((tid & 31) == 0) red[tid >> 5] = sq;
    __syncthreads();
    if (tid == 0) {
        float t = 0.f;
        #pragma unroll
        for (int i = 0; i < 8; i++) t += red[i];
        s_rstd = rsqrtf(t * (1.0f / DD) + 1e-5f);
    }
    __syncthreads();
    float rstd = s_rstd;
    float4 wv = ((const float4*)w)[tid];
    float4 bv = ((const float4*)b)[tid];
    float4 o4;
    o4.x = d0 * rstd * wv.x + bv.x;
    o4.y = d1 * rstd * wv.y + bv.y;
    o4.z = d2 * rstd * wv.z + bv.z;
    o4.w = d3 * rstd * wv.w + bv.w;
    ((float4*)(out + (size_t)row * DD))[tid] = o4;
}

// ---------------------------------------------------------------------------
// Causal flash attention, fp32 SIMT. Q tile 64, KV tile 32, dh=64.
// ---------------------------------------------------------------------------
__global__ void __launch_bounds__(256) attn_kernel(
    const float* __restrict__ qkv, float* __restrict__ out)
{
    __shared__ float Qs[64][68];
    __shared__ float Ks[32][68];
    __shared__ float Vs[32][68];
    __shared__ float Ss[64][36];
    __shared__ float m_s[64], l_s[64], rs_s[64];

    int tid = threadIdx.x;
    int bh = blockIdx.y;
    int b = bh / HH, h = bh % HH;
    int q0 = blockIdx.x * 64;
    const float scale = 0.125f;

    #pragma unroll
    for (int i = 0; i < 4; i++) {
        int f = tid + i * 256;
        int r = f >> 4;
        int c = (f & 15) * 4;
        *(float4*)&Qs[r][c] =
            *(const float4*)&qkv[(size_t)(b * SS + q0 + r) * (3 * DD) + h * DHH + c];
    }
    if (tid < 64) { m_s[tid] = -1e30f; l_s[tid] = 0.f; rs_s[tid] = 0.f; }

    int orow = (tid >> 4) * 4;
    int ocol = (tid & 15) * 4;
    float o[4][4];
    #pragma unroll
    for (int i = 0; i < 4; i++)
        #pragma unroll
        for (int j = 0; j < 4; j++) o[i][j] = 0.f;
    __syncthreads();

    int ntile = 2 * blockIdx.x + 2;
    for (int j = 0; j < ntile; j++) {
        int k0 = j * 32;
        #pragma unroll
        for (int i = 0; i < 2; i++) {
            int f = tid + i * 256;
            int r = f >> 4;
            int c = (f & 15) * 4;
            size_t basei = (size_t)(b * SS + k0 + r) * (3 * DD) + h * DHH + c;
            *(float4*)&Ks[r][c] = *(const float4*)&qkv[basei + DD];
            *(float4*)&Vs[r][c] = *(const float4*)&qkv[basei + 2 * DD];
        }
        __syncthreads();

        {
            int sr = (tid >> 3) * 2;
            int sc = (tid & 7) * 4;
            float s0[4] = {0.f, 0.f, 0.f, 0.f};
            float s1[4] = {0.f, 0.f, 0.f, 0.f};
            #pragma unroll
            for (int k4 = 0; k4 < 16; k4++) {
                float4 qa = *(const float4*)&Qs[sr][k4 * 4];
                float4 qb = *(const float4*)&Qs[sr + 1][k4 * 4];
                #pragma unroll
                for (int cc = 0; cc < 4; cc++) {
                    float4 kv = *(const float4*)&Ks[sc + cc][k4 * 4];
                    s0[cc] = fmaf(qa.x, kv.x, fmaf(qa.y, kv.y, fmaf(qa.z, kv.z, fmaf(qa.w, kv.w, s0[cc]))));
                    s1[cc] = fmaf(qb.x, kv.x, fmaf(qb.y, kv.y, fmaf(qb.z, kv.z, fmaf(qb.w, kv.w, s1[cc]))));
                }
            }
            int qg0 = q0 + sr, qg1 = q0 + sr + 1;
            #pragma unroll
            for (int cc = 0; cc < 4; cc++) {
                int kg = k0 + sc + cc;
                Ss[sr][sc + cc]     = (kg > qg0) ? -1e30f : s0[cc] * scale;
                Ss[sr + 1][sc + cc] = (kg > qg1) ? -1e30f : s1[cc] * scale;
            }
        }
        __syncthreads();

        {
            int r = tid >> 2;
            int part = tid & 3;
            float mx = -1e30f;
            #pragma unroll
            for (int c = 0; c < 8; c++) mx = fmaxf(mx, Ss[r][part * 8 + c]);
            mx = fmaxf(mx, __shfl_xor_sync(0xffffffffu, mx, 1));
            mx = fmaxf(mx, __shfl_xor_sync(0xffffffffu, mx, 2));
            float mold = m_s[r];
            float mnew = fmaxf(mold, mx);
            float sum = 0.f;
            #pragma unroll
            for (int c = 0; c < 8; c++) {
                float p = expf(Ss[r][part * 8 + c] - mnew);
                Ss[r][part * 8 + c] = p;
                sum += p;
            }
            sum += __shfl_xor_sync(0xffffffffu, sum, 1);
            sum += __shfl_xor_sync(0xffffffffu, sum, 2);
            if (part == 0) {
                float rs = expf(mold - mnew);
                l_s[r] = l_s[r] * rs + sum;
                m_s[r] = mnew;
                rs_s[r] = rs;
            }
        }
        __syncthreads();

        #pragma unroll
        for (int i = 0; i < 4; i++) {
            int r = orow + i;
            float rs = rs_s[r];
            o[i][0] *= rs; o[i][1] *= rs; o[i][2] *= rs; o[i][3] *= rs;
            #pragma unroll
            for (int k = 0; k < 32; k++) {
                float p = Ss[r][k];
                float4 vv = *(const float4*)&Vs[k][ocol];
                o[i][0] = fmaf(p, vv.x, o[i][0]);
                o[i][1] = fmaf(p, vv.y, o[i][1]);
                o[i][2] = fmaf(p, vv.z, o[i][2]);
                o[i][3] = fmaf(p, vv.w, o[i][3]);
            }
        }
        __syncthreads();
    }

    #pragma unroll
    for (int i = 0; i < 4; i++) {
        int r = orow + i;
        float inv = 1.0f / l_s[r];
        float4 ov = make_float4(o[i][0] * inv, o[i][1] * inv, o[i][2] * inv, o[i][3] * inv);
        *(float4*)&out[(size_t)(b * SS + q0 + r) * DD + h * DHH + ocol] = ov;
    }
}

// ---------------------------------------------------------------------------
// INL integrator: elementwise, 5 unrolled steps (DT=0.1, TARGET=0)
// ---------------------------------------------------------------------------
__global__ void __launch_bounds__(256) integrate_kernel(
    const float* __restrict__ xs0, const float* __restrict__ u,
    const float* __restrict__ al, const float* __restrict__ be,
    const float* __restrict__ gg, const float* __restrict__ x1,
    float* __restrict__ x2)
{
    int i = blockIdx.x * blockDim.x + threadIdx.x;
    float4 xs = ((const float4*)xs0)[i];
    float4 uu = ((const float4*)u)[i];
    float4 aa = ((const float4*)al)[i];
    float4 bb = ((const float4*)be)[i];
    float4 g4 = ((const float4*)gg)[i];
    float4 r1 = ((const float4*)x1)[i];
    float4 vs = make_float4(0.f, 0.f, 0.f, 0.f);
    const float DT = 0.1f;
    #pragma unroll
    for (int t = 0; t < 5; t++) {
        vs.x += DT * (-aa.x * xs.x - bb.x * vs.x + uu.x);  xs.x += DT * g4.x * vs.x;
        vs.y += DT * (-aa.y * xs.y - bb.y * vs.y + uu.y);  xs.y += DT * g4.y * vs.y;
        vs.z += DT * (-aa.z * xs.z - bb.z * vs.z + uu.z);  xs.z += DT * g4.z * vs.z;
        vs.w += DT * (-aa.w * xs.w - bb.w * vs.w + uu.w);  xs.w += DT * g4.w * vs.w;
    }
    float4 o4 = make_float4(r1.x + xs.x, r1.y + xs.y, r1.z + xs.z, r1.w + xs.w);
    ((float4*)x2)[i] = o4;
}

// ---------------------------------------------------------------------------
// Host launcher
// ---------------------------------------------------------------------------
extern "C" void kernel_launch(void* const* d_in, const int* in_sizes, int n_in,
                              void* d_out, int out_size)
{
    const float* x          = (const float*)d_in[0];
    const float* ln_attn_w  = (const float*)d_in[1];
    const float* ln_attn_b  = (const float*)d_in[2];
    const float* attn_in_w  = (const float*)d_in[3];
    const float* attn_in_b  = (const float*)d_in[4];
    const float* attn_out_w = (const float*)d_in[5];
    const float* attn_out_b = (const float*)d_in[6];
    const float* ln1_w      = (const float*)d_in[7];
    const float* ln1_b      = (const float*)d_in[8];
    const float* ln2_w      = (const float*)d_in[9];
    const float* ln2_b      = (const float*)d_in[10];
    const float* inl_u_w    = (const float*)d_in[11];
    const float* inl_u_b    = (const float*)d_in[12];
    const float* inl_a_w    = (const float*)d_in[13];
    const float* inl_a_b    = (const float*)d_in[14];
    const float* inl_b_w    = (const float*)d_in[15];
    const float* inl_b_b    = (const float*)d_in[16];
    const float* inl_g_w    = (const float*)d_in[17];
    const float* inl_g_b    = (const float*)d_in[18];
    const float* ff1_w      = (const float*)d_in[19];
    const float* ff1_b      = (const float*)d_in[20];
    const float* ff2_w      = (const float*)d_in[21];
    const float* ff2_b      = (const float*)d_in[22];
    float* out = (float*)d_out;

    float *p_ln, *p_qkv, *p_att, *p_ctx, *p_x1, *p_xs, *p_u, *p_al, *p_be, *p_gg, *p_x2, *p_ff;
    cudaGetSymbolAddress((void**)&p_ln,  g_ln);
    cudaGetSymbolAddress((void**)&p_qkv, g_qkv);
    cudaGetSymbolAddress((void**)&p_att, g_att);
    cudaGetSymbolAddress((void**)&p_ctx, g_ctx);
    cudaGetSymbolAddress((void**)&p_x1,  g_x1);
    cudaGetSymbolAddress((void**)&p_xs,  g_xs);
    cudaGetSymbolAddress((void**)&p_u,   g_u);
    cudaGetSymbolAddress((void**)&p_al,  g_al);
    cudaGetSymbolAddress((void**)&p_be,  g_be);
    cudaGetSymbolAddress((void**)&p_gg,  g_gg);
    cudaGetSymbolAddress((void**)&p_x2,  g_x2);
    cudaGetSymbolAddress((void**)&p_ff,  g_ff);

    cudaFuncSetAttribute(gemm_tc<0>, cudaFuncAttributeMaxDynamicSharedMemorySize, GEMM_SMEM);
    cudaFuncSetAttribute(gemm_tc<1>, cudaFuncAttributeMaxDynamicSharedMemorySize, GEMM_SMEM);
    cudaFuncSetAttribute(gemm_tc<2>, cudaFuncAttributeMaxDynamicSharedMemorySize, GEMM_SMEM);
    cudaFuncSetAttribute(gemm_tc<3>, cudaFuncAttributeMaxDynamicSharedMemorySize, GEMM_SMEM);
    cudaFuncSetAttribute(gemm_tc<4>, cudaFuncAttributeMaxDynamicSharedMemorySize, GEMM_SMEM);
    cudaFuncSetAttribute(gemm_tc<5>, cudaFuncAttributeMaxDynamicSharedMemorySize, GEMM_SMEM);

    // 1. ln_attn(x) -> g_ln
    ln_kernel<<<MM, 256>>>(x, ln_attn_w, ln_attn_b, p_ln);
    // 2. qkv = g_ln @ attn_in_w^T + b   [8192,3072]
    gemm_tc<0><<<dim3(3 * DD / 128, MM / 128), 256, GEMM_SMEM>>>(
        p_ln, attn_in_w, attn_in_b, p_qkv, nullptr, nullptr, MM, 3 * DD, DD);
    // 3. causal MHA -> g_att
    attn_kernel<<<dim3(SS / 64, BB * HH), 256>>>(p_qkv, p_att);
    // 4. ctx = g_att @ attn_out_w^T + b ; x1 = x + ctx
    gemm_tc<5><<<dim3(DD / 128, MM / 128), 256, GEMM_SMEM>>>(
        p_att, attn_out_w, attn_out_b, p_ctx, p_x1, x, MM, DD, DD);
    // 5. xs = ln1(x1)
    ln_kernel<<<MM, 256>>>(p_x1, ln1_w, ln1_b, p_xs);
    // 6. INL controllers from ctx
    gemm_tc<0><<<dim3(DD / 128, MM / 128), 256, GEMM_SMEM>>>(
        p_ctx, inl_u_w, inl_u_b, p_u, nullptr, nullptr, MM, DD, DD);
    gemm_tc<2><<<dim3(DD / 128, MM / 128), 256, GEMM_SMEM>>>(
        p_ctx, inl_a_w, inl_a_b, p_al, nullptr, nullptr, MM, DD, DD);
    gemm_tc<3><<<dim3(DD / 128, MM / 128), 256, GEMM_SMEM>>>(
        p_ctx, inl_b_w, inl_b_b, p_be, nullptr, nullptr, MM, DD, DD);
    gemm_tc<2><<<dim3(DD / 128, MM / 128), 256, GEMM_SMEM>>>(
        p_ctx, inl_g_w, inl_g_b, p_gg, nullptr, nullptr, MM, DD, DD);
    // 7. integrate -> x2 = x1 + xs_final
    integrate_kernel<<<(MM * DD / 4) / 256, 256>>>(p_xs, p_u, p_al, p_be, p_gg, p_x1, p_x2);
    // 8. ln2(x2) -> g_ln
    ln_kernel<<<MM, 256>>>(p_x2, ln2_w, ln2_b, p_ln);
    // 9. ff1 + exact GELU -> g_ff   [8192,4096]
    gemm_tc<1><<<dim3(FFD / 128, MM / 128), 256, GEMM_SMEM>>>(
        p_ln, ff1_w, ff1_b, p_ff, nullptr, nullptr, MM, FFD, DD);
    // 10. out = g_ff @ ff2_w^T + b + x2
    gemm_tc<4><<<dim3(DD / 128, MM / 128), 256, GEMM_SMEM>>>(
        p_ff, ff2_w, ff2_b, out, nullptr, p_x2, MM, DD, FFD);
}

// round 5
// speedup vs baseline: 3.1540x; 1.7981x over previous
#include <cuda_runtime.h>
#include <cstdint>
#include <math.h>

// Problem constants
#define BB   4
#define SS   2048
#define DD   1024
#define HH   16
#define DHH  64
#define FFD  4096
#define MM   (BB*SS)      // 8192 rows

// ---------------------------------------------------------------------------
// Scratch (static __device__ — no allocations allowed)
// ---------------------------------------------------------------------------
__device__ float g_ln [MM*DD];
__device__ float g_qkv[MM*3*DD];
__device__ float g_att[MM*DD];
__device__ float g_ctx[MM*DD];
__device__ float g_x1 [MM*DD];
__device__ float g_xs [MM*DD];
__device__ float g_u  [MM*DD];
__device__ float g_al [MM*DD];
__device__ float g_be [MM*DD];
__device__ float g_gg [MM*DD];
__device__ float g_x2 [MM*DD];
__device__ float g_ff [MM*FFD];

// ---------------------------------------------------------------------------
// Helpers
// ---------------------------------------------------------------------------
__device__ __forceinline__ uint32_t smem_u32(const void* p) {
    uint32_t a;
    asm("{ .reg .u64 t; cvta.to.shared.u64 t, %1; cvt.u32.u64 %0, t; }" : "=r"(a) : "l"(p));
    return a;
}
__device__ __forceinline__ uint32_t f2tf32(float f) {
    uint32_t u;
    asm("cvt.rna.tf32.f32 %0, %1;" : "=r"(u) : "f"(f));
    return u;
}
__device__ __forceinline__ uint32_t lds_u32(uint32_t addr) {
    uint32_t v;
    asm volatile("ld.shared.b32 %0, [%1];" : "=r"(v) : "r"(addr));
    return v;
}
__device__ __forceinline__ void sts_u4(uint32_t addr, uint32_t x, uint32_t y, uint32_t z, uint32_t w) {
    asm volatile("st.shared.v4.b32 [%0], {%1,%2,%3,%4};" :: "r"(addr), "r"(x), "r"(y), "r"(z), "r"(w));
}
#define SWZ128(off) ((off) ^ (((off) >> 3) & 0x70))

__device__ __forceinline__ void mma_tf32(float* c, const uint32_t* a, uint32_t b0, uint32_t b1) {
    asm volatile("mma.sync.aligned.m16n8k8.row.col.f32.tf32.tf32.f32 "
        "{%0,%1,%2,%3}, {%4,%5,%6,%7}, {%8,%9}, {%0,%1,%2,%3};"
        : "+f"(c[0]), "+f"(c[1]), "+f"(c[2]), "+f"(c[3])
        : "r"(a[0]), "r"(a[1]), "r"(a[2]), "r"(a[3]), "r"(b0), "r"(b1));
}

// ---------------------------------------------------------------------------
// tf32 tensor GEMM: C[M,N] = A[M,K] @ W[N,K]^T + bias (+ epilogue)
// CTA tile 128x128, 256 threads = 8 warps (4M x 2N), warp tile 32x64.
// K-chunk 32, double-buffered SW128-swizzled smem (2 x 32KB).
// EPI: 0=none 1=gelu 2=sigmoid 3=softplus 4=C=v+res 5=dual(C=v, C2=v+res)
// ---------------------------------------------------------------------------
#define STAGE_BYTES 32768   // A tile 16KB + B tile 16KB
#define GEMM_SMEM   (2 * STAGE_BYTES + 1024)

template<int EPI>
__global__ void __launch_bounds__(256, 2) gemm_tc(
    const float* __restrict__ A, const float* __restrict__ W,
    const float* __restrict__ bias, float* __restrict__ C,
    float* __restrict__ C2, const float* __restrict__ res,
    int M, int N, int K)
{
    extern __shared__ char dsm[];
    uint32_t raw = smem_u32(dsm);
    uint32_t base = (raw + 1023u) & ~1023u;

    int tid = threadIdx.x;
    int wid = tid >> 5, lane = tid & 31;
    int gID = lane >> 2, tig = lane & 3;
    int wm = (wid & 3) * 32;       // warp M offset within tile
    int wn = (wid >> 2) * 64;      // warp N offset within tile

    int rowL[4], colL[4];
    uint32_t stsOff[4];
    #pragma unroll
    for (int i = 0; i < 4; i++) {
        int f = tid + i * 256;
        rowL[i] = f >> 3;
        colL[i] = (f & 7) * 4;
        stsOff[i] = SWZ128((uint32_t)(rowL[i] * 128 + colL[i] * 4));
    }
    const float* Abase = A + (size_t)(blockIdx.y * 128) * K;
    const float* Wbase = W + (size_t)(blockIdx.x * 128) * K;

    float acc[2][8][4];
    #pragma unroll
    for (int mi = 0; mi < 2; mi++)
        #pragma unroll
        for (int ni = 0; ni < 8; ni++)
            #pragma unroll
            for (int j = 0; j < 4; j++) acc[mi][ni][j] = 0.f;

    const int niter = K / 32;
    float4 ra[4], rb[4];

    #pragma unroll
    for (int i = 0; i < 4; i++) {
        ra[i] = *(const float4*)(Abase + (size_t)rowL[i] * K + colL[i]);
        rb[i] = *(const float4*)(Wbase + (size_t)rowL[i] * K + colL[i]);
    }
    #pragma unroll
    for (int i = 0; i < 4; i++) {
        sts_u4(base + stsOff[i], f2tf32(ra[i].x), f2tf32(ra[i].y), f2tf32(ra[i].z), f2tf32(ra[i].w));
        sts_u4(base + 16384 + stsOff[i], f2tf32(rb[i].x), f2tf32(rb[i].y), f2tf32(rb[i].z), f2tf32(rb[i].w));
    }
    __syncthreads();

    for (int it = 0; it < niter; it++) {
        int st = it & 1;
        uint32_t sA = base + st * STAGE_BYTES;
        uint32_t sB = sA + 16384;

        if (it + 1 < niter) {
            int kt = (it + 1) * 32;
            #pragma unroll
            for (int i = 0; i < 4; i++) {
                ra[i] = *(const float4*)(Abase + (size_t)rowL[i] * K + kt + colL[i]);
                rb[i] = *(const float4*)(Wbase + (size_t)rowL[i] * K + kt + colL[i]);
            }
        }

        #pragma unroll
        for (int s = 0; s < 4; s++) {
            int cb = s * 32 + tig * 4;
            uint32_t afr[2][4];
            #pragma unroll
            for (int mi = 0; mi < 2; mi++) {
                int r = wm + mi * 16 + gID;
                afr[mi][0] = lds_u32(sA + SWZ128((uint32_t)(r * 128 + cb)));
                afr[mi][1] = lds_u32(sA + SWZ128((uint32_t)((r + 8) * 128 + cb)));
                afr[mi][2] = lds_u32(sA + SWZ128((uint32_t)(r * 128 + cb + 16)));
                afr[mi][3] = lds_u32(sA + SWZ128((uint32_t)((r + 8) * 128 + cb + 16)));
            }
            #pragma unroll
            for (int ni = 0; ni < 8; ni++) {
                int n = wn + ni * 8 + gID;
                uint32_t b0 = lds_u32(sB + SWZ128((uint32_t)(n * 128 + cb)));
                uint32_t b1 = lds_u32(sB + SWZ128((uint32_t)(n * 128 + cb + 16)));
                mma_tf32(acc[0][ni], afr[0], b0, b1);
                mma_tf32(acc[1][ni], afr[1], b0, b1);
            }
        }
        __syncthreads();

        if (it + 1 < niter) {
            uint32_t dA = base + (st ^ 1) * STAGE_BYTES;
            #pragma unroll
            for (int i = 0; i < 4; i++) {
                sts_u4(dA + stsOff[i], f2tf32(ra[i].x), f2tf32(ra[i].y), f2tf32(ra[i].z), f2tf32(ra[i].w));
                sts_u4(dA + 16384 + stsOff[i], f2tf32(rb[i].x), f2tf32(rb[i].y), f2tf32(rb[i].z), f2tf32(rb[i].w));
            }
            __syncthreads();
        }
    }

    int row0 = blockIdx.y * 128 + wm + gID;
    int col0 = blockIdx.x * 128 + wn;
    #pragma unroll
    for (int mi = 0; mi < 2; mi++) {
        #pragma unroll
        for (int half = 0; half < 2; half++) {
            int r = row0 + mi * 16 + half * 8;
            size_t rbase = (size_t)r * N;
            #pragma unroll
            for (int ni = 0; ni < 8; ni++) {
                int c = col0 + ni * 8 + 2 * tig;
                float v0 = acc[mi][ni][half * 2 + 0] + bias[c];
                float v1 = acc[mi][ni][half * 2 + 1] + bias[c + 1];
                if (EPI == 1) {
                    v0 = 0.5f * v0 * (1.0f + erff(v0 * 0.70710678118654752f));
                    v1 = 0.5f * v1 * (1.0f + erff(v1 * 0.70710678118654752f));
                } else if (EPI == 2) {
                    v0 = 1.0f / (1.0f + expf(-v0));
                    v1 = 1.0f / (1.0f + expf(-v1));
                } else if (EPI == 3) {
                    v0 = (v0 > 0.f) ? (v0 + log1pf(expf(-v0))) : log1pf(expf(v0));
                    v1 = (v1 > 0.f) ? (v1 + log1pf(expf(-v1))) : log1pf(expf(v1));
                }
                if (EPI == 4) {
                    float2 r2 = *(const float2*)(res + rbase + c);
                    *(float2*)(C + rbase + c) = make_float2(v0 + r2.x, v1 + r2.y);
                } else if (EPI == 5) {
                    float2 r2 = *(const float2*)(res + rbase + c);
                    *(float2*)(C + rbase + c)  = make_float2(v0, v1);
                    *(float2*)(C2 + rbase + c) = make_float2(v0 + r2.x, v1 + r2.y);
                } else {
                    *(float2*)(C + rbase + c) = make_float2(v0, v1);
                }
            }
        }
    }
}

// ---------------------------------------------------------------------------
// Tensor-core causal flash attention (tf32 mma).
// Q tile 64 per CTA (4 warps x m16), KV tile 64, dh=64.
// K/V/P in smem, pitch 72 floats (conflict-free for all fragment patterns).
// Q fragments preloaded to registers. Online softmax in C-fragment registers.
// ---------------------------------------------------------------------------
#define PITCH 72
#define ATT_SMEM (3 * 64 * PITCH * 4)

__global__ void __launch_bounds__(128) attn_tc_kernel(
    const float* __restrict__ qkv, float* __restrict__ out)
{
    extern __shared__ float sm[];
    float* Ks = sm;
    float* Vs = sm + 64 * PITCH;
    float* Ps = sm + 2 * 64 * PITCH;

    int tid = threadIdx.x;
    int wid = tid >> 5, lane = tid & 31;
    int gID = lane >> 2, tig = lane & 3;
    int b = blockIdx.y >> 4, h = blockIdx.y & 15;
    int q0 = blockIdx.x * 64;
    const float scale = 0.125f;   // 1/sqrt(64), exact power of 2

    // Load Q tile (scaled, tf32-rounded) into Ps staging
    #pragma unroll
    for (int i = 0; i < 8; i++) {
        int f = tid + i * 128;
        int r = f >> 4;
        int c = (f & 15) * 4;
        float4 v = *(const float4*)&qkv[(size_t)(b * SS + q0 + r) * (3 * DD) + h * DHH + c];
        uint32_t* dst = (uint32_t*)&Ps[r * PITCH + c];
        dst[0] = f2tf32(v.x * scale); dst[1] = f2tf32(v.y * scale);
        dst[2] = f2tf32(v.z * scale); dst[3] = f2tf32(v.w * scale);
    }
    __syncthreads();

    // Preload Q fragments: rows rA, rA+8 of this warp, all 8 k-steps
    int rA = wid * 16 + gID;
    uint32_t qf[8][4];
    #pragma unroll
    for (int s = 0; s < 8; s++) {
        qf[s][0] = __float_as_uint(Ps[rA * PITCH + 8 * s + tig]);
        qf[s][1] = __float_as_uint(Ps[(rA + 8) * PITCH + 8 * s + tig]);
        qf[s][2] = __float_as_uint(Ps[rA * PITCH + 8 * s + tig + 4]);
        qf[s][3] = __float_as_uint(Ps[(rA + 8) * PITCH + 8 * s + tig + 4]);
    }

    float of[8][4];
    #pragma unroll
    for (int ni = 0; ni < 8; ni++)
        #pragma unroll
        for (int j = 0; j < 4; j++) of[ni][j] = 0.f;
    float m0 = -1e30f, m1 = -1e30f, l0 = 0.f, l1 = 0.f;

    int nt = blockIdx.x + 1;
    for (int jt = 0; jt < nt; jt++) {
        int k0 = jt * 64;
        __syncthreads();   // all warps done with previous K/V (and Q staging on iter 0)
        // Load K/V tiles (tf32-rounded)
        #pragma unroll
        for (int i = 0; i < 8; i++) {
            int f = tid + i * 128;
            int r = f >> 4;
            int c = (f & 15) * 4;
            size_t gb = (size_t)(b * SS + k0 + r) * (3 * DD) + h * DHH + c;
            float4 kv = *(const float4*)&qkv[gb + DD];
            float4 vv = *(const float4*)&qkv[gb + 2 * DD];
            uint32_t* dk = (uint32_t*)&Ks[r * PITCH + c];
            dk[0] = f2tf32(kv.x); dk[1] = f2tf32(kv.y); dk[2] = f2tf32(kv.z); dk[3] = f2tf32(kv.w);
            uint32_t* dv = (uint32_t*)&Vs[r * PITCH + c];
            dv[0] = f2tf32(vv.x); dv[1] = f2tf32(vv.y); dv[2] = f2tf32(vv.z); dv[3] = f2tf32(vv.w);
        }
        __syncthreads();

        // S = Q @ K^T  (scaled via Q)
        float sc[8][4];
        #pragma unroll
        for (int ni = 0; ni < 8; ni++)
            #pragma unroll
            for (int j = 0; j < 4; j++) sc[ni][j] = 0.f;
        #pragma unroll
        for (int s = 0; s < 8; s++) {
            #pragma unroll
            for (int ni = 0; ni < 8; ni++) {
                uint32_t b0 = __float_as_uint(Ks[(ni * 8 + gID) * PITCH + 8 * s + tig]);
                uint32_t b1 = __float_as_uint(Ks[(ni * 8 + gID) * PITCH + 8 * s + tig + 4]);
                mma_tf32(sc[ni], qf[s], b0, b1);
            }
        }

        // Causal mask (only diagonal tile; k0 == q0 there)
        if (jt == nt - 1) {
            #pragma unroll
            for (int ni = 0; ni < 8; ni++) {
                int ct = ni * 8 + 2 * tig;
                if (ct > rA)         sc[ni][0] = -1e30f;
                if (ct + 1 > rA)     sc[ni][1] = -1e30f;
                if (ct > rA + 8)     sc[ni][2] = -1e30f;
                if (ct + 1 > rA + 8) sc[ni][3] = -1e30f;
            }
        }

        // Online softmax (rows rA via c0/c1, rA+8 via c2/c3)
        float mx0 = -1e30f, mx1 = -1e30f;
        #pragma unroll
        for (int ni = 0; ni < 8; ni++) {
            mx0 = fmaxf(mx0, fmaxf(sc[ni][0], sc[ni][1]));
            mx1 = fmaxf(mx1, fmaxf(sc[ni][2], sc[ni][3]));
        }
        mx0 = fmaxf(mx0, __shfl_xor_sync(0xffffffffu, mx0, 1));
        mx0 = fmaxf(mx0, __shfl_xor_sync(0xffffffffu, mx0, 2));
        mx1 = fmaxf(mx1, __shfl_xor_sync(0xffffffffu, mx1, 1));
        mx1 = fmaxf(mx1, __shfl_xor_sync(0xffffffffu, mx1, 2));
        float mn0 = fmaxf(m0, mx0), mn1 = fmaxf(m1, mx1);
        float rs0 = expf(m0 - mn0), rs1 = expf(m1 - mn1);
        m0 = mn0; m1 = mn1;

        float sum0 = 0.f, sum1 = 0.f;
        #pragma unroll
        for (int ni = 0; ni < 8; ni++) {
            sc[ni][0] = expf(sc[ni][0] - mn0);
            sc[ni][1] = expf(sc[ni][1] - mn0);
            sc[ni][2] = expf(sc[ni][2] - mn1);
            sc[ni][3] = expf(sc[ni][3] - mn1);
            sum0 += sc[ni][0] + sc[ni][1];
            sum1 += sc[ni][2] + sc[ni][3];
        }
        sum0 += __shfl_xor_sync(0xffffffffu, sum0, 1);
        sum0 += __shfl_xor_sync(0xffffffffu, sum0, 2);
        sum1 += __shfl_xor_sync(0xffffffffu, sum1, 1);
        sum1 += __shfl_xor_sync(0xffffffffu, sum1, 2);
        l0 = l0 * rs0 + sum0;
        l1 = l1 * rs1 + sum1;

        // Rescale O accumulators
        #pragma unroll
        for (int ni = 0; ni < 8; ni++) {
            of[ni][0] *= rs0; of[ni][1] *= rs0;
            of[ni][2] *= rs1; of[ni][3] *= rs1;
        }

        // Write P (tf32) to per-warp private smem (C-layout -> A-layout staging)
        #pragma unroll
        for (int ni = 0; ni < 8; ni++) {
            uint32_t* p0 = (uint32_t*)&Ps[rA * PITCH + ni * 8 + 2 * tig];
            p0[0] = f2tf32(sc[ni][0]); p0[1] = f2tf32(sc[ni][1]);
            uint32_t* p1 = (uint32_t*)&Ps[(rA + 8) * PITCH + ni * 8 + 2 * tig];
            p1[0] = f2tf32(sc[ni][2]); p1[1] = f2tf32(sc[ni][3]);
        }
        __syncwarp();

        // O += P @ V
        #pragma unroll
        for (int s = 0; s < 8; s++) {
            uint32_t pa[4];
            pa[0] = __float_as_uint(Ps[rA * PITCH + 8 * s + tig]);
            pa[1] = __float_as_uint(Ps[(rA + 8) * PITCH + 8 * s + tig]);
            pa[2] = __float_as_uint(Ps[rA * PITCH + 8 * s + tig + 4]);
            pa[3] = __float_as_uint(Ps[(rA + 8) * PITCH + 8 * s + tig + 4]);
            #pragma unroll
            for (int ni = 0; ni < 8; ni++) {
                uint32_t b0 = __float_as_uint(Vs[(8 * s + tig) * PITCH + ni * 8 + gID]);
                uint32_t b1 = __float_as_uint(Vs[(8 * s + tig + 4) * PITCH + ni * 8 + gID]);
                mma_tf32(of[ni], pa, b0, b1);
            }
        }
        __syncwarp();   // P reads done before next tile's P writes
    }

    // Normalize and store
    float inv0 = 1.0f / l0, inv1 = 1.0f / l1;
    size_t row0 = (size_t)(b * SS + q0 + rA);
    #pragma unroll
    for (int ni = 0; ni < 8; ni++) {
        int d = h * DHH + ni * 8 + 2 * tig;
        *(float2*)&out[row0 * DD + d]       = make_float2(of[ni][0] * inv0, of[ni][1] * inv0);
        *(float2*)&out[(row0 + 8) * DD + d] = make_float2(of[ni][2] * inv1, of[ni][3] * inv1);
    }
}

// ---------------------------------------------------------------------------
// LayerNorm: one block per row (D=1024, 256 threads, 4 floats/thread)
// ---------------------------------------------------------------------------
__global__ void __launch_bounds__(256) ln_kernel(
    const float* __restrict__ x, const float* __restrict__ w,
    const float* __restrict__ b, float* __restrict__ out)
{
    int row = blockIdx.x;
    int tid = threadIdx.x;
    const float4* xr = (const float4*)(x + (size_t)row * DD);
    float4 v = xr[tid];

    __shared__ float red[8];
    float s = v.x + v.y + v.z + v.w;
    #pragma unroll
    for (int o = 16; o > 0; o >>= 1) s += __shfl_xor_sync(0xffffffffu, s, o);
    if ((tid & 31) == 0) red[tid >> 5] = s;
    __syncthreads();
    __shared__ float s_mean, s_rstd;
    if (tid == 0) {
        float t = 0.f;
        #pragma unroll
        for (int i = 0; i < 8; i++) t += red[i];
        s_mean = t * (1.0f / DD);
    }
    __syncthreads();
    float mean = s_mean;
    float d0 = v.x - mean, d1 = v.y - mean, d2 = v.z - mean, d3 = v.w - mean;
    float sq = d0*d0 + d1*d1 + d2*d2 + d3*d3;
    #pragma unroll
    for (int o = 16; o > 0; o >>= 1) sq += __shfl_xor_sync(0xffffffffu, sq, o);
    __syncthreads();
    if ((tid & 31) == 0) red[tid >> 5] = sq;
    __syncthreads();
    if (tid == 0) {
        float t = 0.f;
        #pragma unroll
        for (int i = 0; i < 8; i++) t += red[i];
        s_rstd = rsqrtf(t * (1.0f / DD) + 1e-5f);
    }
    __syncthreads();
    float rstd = s_rstd;
    float4 wv = ((const float4*)w)[tid];
    float4 bv = ((const float4*)b)[tid];
    float4 o4;
    o4.x = d0 * rstd * wv.x + bv.x;
    o4.y = d1 * rstd * wv.y + bv.y;
    o4.z = d2 * rstd * wv.z + bv.z;
    o4.w = d3 * rstd * wv.w + bv.w;
    ((float4*)(out + (size_t)row * DD))[tid] = o4;
}

// ---------------------------------------------------------------------------
// INL integrator: elementwise, 5 unrolled steps (DT=0.1, TARGET=0)
// ---------------------------------------------------------------------------
__global__ void __launch_bounds__(256) integrate_kernel(
    const float* __restrict__ xs0, const float* __restrict__ u,
    const float* __restrict__ al, const float* __restrict__ be,
    const float* __restrict__ gg, const float* __restrict__ x1,
    float* __restrict__ x2)
{
    int i = blockIdx.x * blockDim.x + threadIdx.x;
    float4 xs = ((const float4*)xs0)[i];
    float4 uu = ((const float4*)u)[i];
    float4 aa = ((const float4*)al)[i];
    float4 bb = ((const float4*)be)[i];
    float4 g4 = ((const float4*)gg)[i];
    float4 r1 = ((const float4*)x1)[i];
    float4 vs = make_float4(0.f, 0.f, 0.f, 0.f);
    const float DT = 0.1f;
    #pragma unroll
    for (int t = 0; t < 5; t++) {
        vs.x += DT * (-aa.x * xs.x - bb.x * vs.x + uu.x);  xs.x += DT * g4.x * vs.x;
        vs.y += DT * (-aa.y * xs.y - bb.y * vs.y + uu.y);  xs.y += DT * g4.y * vs.y;
        vs.z += DT * (-aa.z * xs.z - bb.z * vs.z + uu.z);  xs.z += DT * g4.z * vs.z;
        vs.w += DT * (-aa.w * xs.w - bb.w * vs.w + uu.w);  xs.w += DT * g4.w * vs.w;
    }
    float4 o4 = make_float4(r1.x + xs.x, r1.y + xs.y, r1.z + xs.z, r1.w + xs.w);
    ((float4*)x2)[i] = o4;
}

// ---------------------------------------------------------------------------
// Host launcher
// ---------------------------------------------------------------------------
extern "C" void kernel_launch(void* const* d_in, const int* in_sizes, int n_in,
                              void* d_out, int out_size)
{
    const float* x          = (const float*)d_in[0];
    const float* ln_attn_w  = (const float*)d_in[1];
    const float* ln_attn_b  = (const float*)d_in[2];
    const float* attn_in_w  = (const float*)d_in[3];
    const float* attn_in_b  = (const float*)d_in[4];
    const float* attn_out_w = (const float*)d_in[5];
    const float* attn_out_b = (const float*)d_in[6];
    const float* ln1_w      = (const float*)d_in[7];
    const float* ln1_b      = (const float*)d_in[8];
    const float* ln2_w      = (const float*)d_in[9];
    const float* ln2_b      = (const float*)d_in[10];
    const float* inl_u_w    = (const float*)d_in[11];
    const float* inl_u_b    = (const float*)d_in[12];
    const float* inl_a_w    = (const float*)d_in[13];
    const float* inl_a_b    = (const float*)d_in[14];
    const float* inl_b_w    = (const float*)d_in[15];
    const float* inl_b_b    = (const float*)d_in[16];
    const float* inl_g_w    = (const float*)d_in[17];
    const float* inl_g_b    = (const float*)d_in[18];
    const float* ff1_w      = (const float*)d_in[19];
    const float* ff1_b      = (const float*)d_in[20];
    const float* ff2_w      = (const float*)d_in[21];
    const float* ff2_b      = (const float*)d_in[22];
    float* out = (float*)d_out;

    float *p_ln, *p_qkv, *p_att, *p_ctx, *p_x1, *p_xs, *p_u, *p_al, *p_be, *p_gg, *p_x2, *p_ff;
    cudaGetSymbolAddress((void**)&p_ln,  g_ln);
    cudaGetSymbolAddress((void**)&p_qkv, g_qkv);
    cudaGetSymbolAddress((void**)&p_att, g_att);
    cudaGetSymbolAddress((void**)&p_ctx, g_ctx);
    cudaGetSymbolAddress((void**)&p_x1,  g_x1);
    cudaGetSymbolAddress((void**)&p_xs,  g_xs);
    cudaGetSymbolAddress((void**)&p_u,   g_u);
    cudaGetSymbolAddress((void**)&p_al,  g_al);
    cudaGetSymbolAddress((void**)&p_be,  g_be);
    cudaGetSymbolAddress((void**)&p_gg,  g_gg);
    cudaGetSymbolAddress((void**)&p_x2,  g_x2);
    cudaGetSymbolAddress((void**)&p_ff,  g_ff);

    cudaFuncSetAttribute(gemm_tc<0>, cudaFuncAttributeMaxDynamicSharedMemorySize, GEMM_SMEM);
    cudaFuncSetAttribute(gemm_tc<1>, cudaFuncAttributeMaxDynamicSharedMemorySize, GEMM_SMEM);
    cudaFuncSetAttribute(gemm_tc<2>, cudaFuncAttributeMaxDynamicSharedMemorySize, GEMM_SMEM);
    cudaFuncSetAttribute(gemm_tc<3>, cudaFuncAttributeMaxDynamicSharedMemorySize, GEMM_SMEM);
    cudaFuncSetAttribute(gemm_tc<4>, cudaFuncAttributeMaxDynamicSharedMemorySize, GEMM_SMEM);
    cudaFuncSetAttribute(gemm_tc<5>, cudaFuncAttributeMaxDynamicSharedMemorySize, GEMM_SMEM);
    cudaFuncSetAttribute(attn_tc_kernel, cudaFuncAttributeMaxDynamicSharedMemorySize, ATT_SMEM);

    // 1. ln_attn(x) -> g_ln
    ln_kernel<<<MM, 256>>>(x, ln_attn_w, ln_attn_b, p_ln);
    // 2. qkv = g_ln @ attn_in_w^T + b   [8192,3072]
    gemm_tc<0><<<dim3(3 * DD / 128, MM / 128), 256, GEMM_SMEM>>>(
        p_ln, attn_in_w, attn_in_b, p_qkv, nullptr, nullptr, MM, 3 * DD, DD);
    // 3. causal MHA (tensor core) -> g_att
    attn_tc_kernel<<<dim3(SS / 64, BB * HH), 128, ATT_SMEM>>>(p_qkv, p_att);
    // 4. ctx = g_att @ attn_out_w^T + b ; x1 = x + ctx
    gemm_tc<5><<<dim3(DD / 128, MM / 128), 256, GEMM_SMEM>>>(
        p_att, attn_out_w, attn_out_b, p_ctx, p_x1, x, MM, DD, DD);
    // 5. xs = ln1(x1)
    ln_kernel<<<MM, 256>>>(p_x1, ln1_w, ln1_b, p_xs);
    // 6. INL controllers from ctx
    gemm_tc<0><<<dim3(DD / 128, MM / 128), 256, GEMM_SMEM>>>(
        p_ctx, inl_u_w, inl_u_b, p_u, nullptr, nullptr, MM, DD, DD);
    gemm_tc<2><<<dim3(DD / 128, MM / 128), 256, GEMM_SMEM>>>(
        p_ctx, inl_a_w, inl_a_b, p_al, nullptr, nullptr, MM, DD, DD);
    gemm_tc<3><<<dim3(DD / 128, MM / 128), 256, GEMM_SMEM>>>(
        p_ctx, inl_b_w, inl_b_b, p_be, nullptr, nullptr, MM, DD, DD);
    gemm_tc<2><<<dim3(DD / 128, MM / 128), 256, GEMM_SMEM>>>(
        p_ctx, inl_g_w, inl_g_b, p_gg, nullptr, nullptr, MM, DD, DD);
    // 7. integrate -> x2 = x1 + xs_final
    integrate_kernel<<<(MM * DD / 4) / 256, 256>>>(p_xs, p_u, p_al, p_be, p_gg, p_x1, p_x2);
    // 8. ln2(x2) -> g_ln
    ln_kernel<<<MM, 256>>>(p_x2, ln2_w, ln2_b, p_ln);
    // 9. ff1 + exact GELU -> g_ff   [8192,4096]
    gemm_tc<1><<<dim3(FFD / 128, MM / 128), 256, GEMM_SMEM>>>(
        p_ln, ff1_w, ff1_b, p_ff, nullptr, nullptr, MM, FFD, DD);
    // 10. out = g_ff @ ff2_w^T + b + x2
    gemm_tc<4><<<dim3(DD / 128, MM / 128), 256, GEMM_SMEM>>>(
        p_ff, ff2_w, ff2_b, out, nullptr, p_x2, MM, DD, FFD);
}

// round 6
// speedup vs baseline: 3.6500x; 1.1573x over previous
#include <cuda_runtime.h>
#include <cstdint>
#include <math.h>

// Problem constants
#define BB   4
#define SS   2048
#define DD   1024
#define HH   16
#define DHH  64
#define FFD  4096
#define MM   (BB*SS)      // 8192 rows

// ---------------------------------------------------------------------------
// Scratch (static __device__ — no allocations allowed)
// ---------------------------------------------------------------------------
__device__ float g_ln [MM*DD];
__device__ float g_qkv[MM*3*DD];
__device__ float g_att[MM*DD];
__device__ float g_ctx[MM*DD];
__device__ float g_x1 [MM*DD];
__device__ float g_xs [MM*DD];
__device__ float g_u  [MM*DD];
__device__ float g_al [MM*DD];
__device__ float g_be [MM*DD];
__device__ float g_gg [MM*DD];
__device__ float g_x2 [MM*DD];
__device__ float g_ff [MM*FFD];

// ---------------------------------------------------------------------------
// Helpers
// ---------------------------------------------------------------------------
__device__ __forceinline__ uint32_t smem_u32(const void* p) {
    uint32_t a;
    asm("{ .reg .u64 t; cvta.to.shared.u64 t, %1; cvt.u32.u64 %0, t; }" : "=r"(a) : "l"(p));
    return a;
}
__device__ __forceinline__ uint32_t f2tf32(float f) {
    uint32_t u;
    asm("cvt.rna.tf32.f32 %0, %1;" : "=r"(u) : "f"(f));
    return u;
}
__device__ __forceinline__ uint32_t lds_u32(uint32_t addr) {
    uint32_t v;
    asm volatile("ld.shared.b32 %0, [%1];" : "=r"(v) : "r"(addr));
    return v;
}
__device__ __forceinline__ void sts_u4(uint32_t addr, uint32_t x, uint32_t y, uint32_t z, uint32_t w) {
    asm volatile("st.shared.v4.b32 [%0], {%1,%2,%3,%4};" :: "r"(addr), "r"(x), "r"(y), "r"(z), "r"(w));
}
#define SWZ128(off) ((off) ^ (((off) >> 3) & 0x70))

__device__ __forceinline__ void mma_tf32(float* c, const uint32_t* a, uint32_t b0, uint32_t b1) {
    asm volatile("mma.sync.aligned.m16n8k8.row.col.f32.tf32.tf32.f32 "
        "{%0,%1,%2,%3}, {%4,%5,%6,%7}, {%8,%9}, {%0,%1,%2,%3};"
        : "+f"(c[0]), "+f"(c[1]), "+f"(c[2]), "+f"(c[3])
        : "r"(a[0]), "r"(a[1]), "r"(a[2]), "r"(a[3]), "r"(b0), "r"(b1));
}

// ---------------------------------------------------------------------------
// tf32 tensor GEMM: C[M,N] = A[M,K] @ W[N,K]^T + bias (+ epilogue)
// CTA tile 128x128, 128 threads = 4 warps (2M x 2N), warp tile 64x64.
// K-chunk 32, double-buffered SW128-swizzled smem (2 x 32KB), one barrier/chunk.
// All fragment rows satisfy (row & 7) == gID -> swizzle XOR mask = gID<<4 (const).
// EPI: 0=none 1=gelu 2=sigmoid 3=softplus 4=C=v+res 5=dual(C=v, C2=v+res)
// ---------------------------------------------------------------------------
#define STAGE_BYTES 32768   // A tile 16KB + B tile 16KB
#define GEMM_SMEM   (2 * STAGE_BYTES + 1024)

template<int EPI>
__global__ void __launch_bounds__(128, 2) gemm_tc(
    const float* __restrict__ A, const float* __restrict__ W,
    const float* __restrict__ bias, float* __restrict__ C,
    float* __restrict__ C2, const float* __restrict__ res,
    int M, int N, int K)
{
    extern __shared__ char dsm[];
    uint32_t raw = smem_u32(dsm);
    uint32_t base = (raw + 1023u) & ~1023u;

    int tid = threadIdx.x;
    int wid = tid >> 5, lane = tid & 31;
    int gID = lane >> 2, tig = lane & 3;
    int wm = (wid & 1) * 64;       // warp M offset
    int wn = (wid >> 1) * 64;      // warp N offset

    // Staging map: f = tid + i*128 (i<8) covers 128 rows x 8 float4.
    // row = f>>3, colf4 = f&7. Linear in i: gOff += 16*K, sOff += 2048.
    const int f0 = tid;
    const uint32_t gOff0 = (uint32_t)((f0 >> 3) * K + (f0 & 7) * 4);
    const uint32_t gStep = (uint32_t)(16 * K);
    const uint32_t sOff0 = SWZ128((uint32_t)((f0 >> 3) * 128 + (f0 & 7) * 16));

    const float* Abase = A + (size_t)(blockIdx.y * 128) * K;
    const float* Wbase = W + (size_t)(blockIdx.x * 128) * K;

    const uint32_t rowA0 = (uint32_t)((wm + gID) * 128);   // + mi*2048, +1024 for r+8
    const uint32_t rowB0 = (uint32_t)((wn + gID) * 128);   // + ni*1024
    const uint32_t xmask = (uint32_t)(gID << 4);

    float acc[4][8][4];
    #pragma unroll
    for (int mi = 0; mi < 4; mi++)
        #pragma unroll
        for (int ni = 0; ni < 8; ni++)
            #pragma unroll
            for (int j = 0; j < 4; j++) acc[mi][ni][j] = 0.f;

    const int niter = K / 32;
    float4 ra[8], rb[8];

    // Preload chunk 0 into stage 0
    #pragma unroll
    for (int i = 0; i < 8; i++) ra[i] = *(const float4*)(Abase + gOff0 + i * gStep);
    #pragma unroll
    for (int i = 0; i < 8; i++) rb[i] = *(const float4*)(Wbase + gOff0 + i * gStep);
    #pragma unroll
    for (int i = 0; i < 8; i++) {
        sts_u4(base + sOff0 + i * 2048,
               f2tf32(ra[i].x), f2tf32(ra[i].y), f2tf32(ra[i].z), f2tf32(ra[i].w));
        sts_u4(base + 16384 + sOff0 + i * 2048,
               f2tf32(rb[i].x), f2tf32(rb[i].y), f2tf32(rb[i].z), f2tf32(rb[i].w));
    }
    __syncthreads();

    for (int it = 0; it < niter; it++) {
        uint32_t sA = base + (uint32_t)(it & 1) * STAGE_BYTES;
        uint32_t sB = sA + 16384;
        uint32_t dA = base + (uint32_t)((it + 1) & 1) * STAGE_BYTES;
        bool pf = (it + 1 < niter);
        const float* An = Abase + (it + 1) * 32;
        const float* Wn = Wbase + (it + 1) * 32;

        if (pf) {
            #pragma unroll
            for (int i = 0; i < 8; i++) ra[i] = *(const float4*)(An + gOff0 + i * gStep);
        }

        #pragma unroll
        for (int s = 0; s < 4; s++) {
            uint32_t x0 = ((uint32_t)(s * 32 + tig * 4)) ^ xmask;
            uint32_t x1 = x0 ^ 16u;
            uint32_t aB0 = sA + rowA0 + x0;
            uint32_t aB1 = sA + rowA0 + x1;
            uint32_t bB0 = sB + rowB0 + x0;
            uint32_t bB1 = sB + rowB0 + x1;

            uint32_t af[4][4];
            #pragma unroll
            for (int mi = 0; mi < 4; mi++) {
                af[mi][0] = lds_u32(aB0 + mi * 2048);
                af[mi][1] = lds_u32(aB0 + mi * 2048 + 1024);
                af[mi][2] = lds_u32(aB1 + mi * 2048);
                af[mi][3] = lds_u32(aB1 + mi * 2048 + 1024);
            }
            #pragma unroll
            for (int ni = 0; ni < 8; ni++) {
                uint32_t b0 = lds_u32(bB0 + ni * 1024);
                uint32_t b1 = lds_u32(bB1 + ni * 1024);
                #pragma unroll
                for (int mi = 0; mi < 4; mi++)
                    mma_tf32(acc[mi][ni], af[mi], b0, b1);
            }

            if (s == 0 && pf) {
                #pragma unroll
                for (int i = 0; i < 8; i++)
                    sts_u4(dA + sOff0 + i * 2048,
                           f2tf32(ra[i].x), f2tf32(ra[i].y), f2tf32(ra[i].z), f2tf32(ra[i].w));
                #pragma unroll
                for (int i = 0; i < 8; i++) rb[i] = *(const float4*)(Wn + gOff0 + i * gStep);
            }
            if (s == 2 && pf) {
                #pragma unroll
                for (int i = 0; i < 8; i++)
                    sts_u4(dA + 16384 + sOff0 + i * 2048,
                           f2tf32(rb[i].x), f2tf32(rb[i].y), f2tf32(rb[i].z), f2tf32(rb[i].w));
            }
        }
        __syncthreads();
    }

    // Epilogue: c0,c1 at (row = wm+mi*16+gID, col = wn+ni*8+2*tig); c2,c3 at row+8.
    int row0 = blockIdx.y * 128 + wm + gID;
    int col0 = blockIdx.x * 128 + wn;
    #pragma unroll
    for (int mi = 0; mi < 4; mi++) {
        #pragma unroll
        for (int half = 0; half < 2; half++) {
            int r = row0 + mi * 16 + half * 8;
            size_t rbase = (size_t)r * N;
            #pragma unroll
            for (int ni = 0; ni < 8; ni++) {
                int c = col0 + ni * 8 + 2 * tig;
                float v0 = acc[mi][ni][half * 2 + 0] + bias[c];
                float v1 = acc[mi][ni][half * 2 + 1] + bias[c + 1];
                if (EPI == 1) {
                    v0 = 0.5f * v0 * (1.0f + erff(v0 * 0.70710678118654752f));
                    v1 = 0.5f * v1 * (1.0f + erff(v1 * 0.70710678118654752f));
                } else if (EPI == 2) {
                    v0 = 1.0f / (1.0f + expf(-v0));
                    v1 = 1.0f / (1.0f + expf(-v1));
                } else if (EPI == 3) {
                    v0 = (v0 > 0.f) ? (v0 + log1pf(expf(-v0))) : log1pf(expf(v0));
                    v1 = (v1 > 0.f) ? (v1 + log1pf(expf(-v1))) : log1pf(expf(v1));
                }
                if (EPI == 4) {
                    float2 r2 = *(const float2*)(res + rbase + c);
                    *(float2*)(C + rbase + c) = make_float2(v0 + r2.x, v1 + r2.y);
                } else if (EPI == 5) {
                    float2 r2 = *(const float2*)(res + rbase + c);
                    *(float2*)(C + rbase + c)  = make_float2(v0, v1);
                    *(float2*)(C2 + rbase + c) = make_float2(v0 + r2.x, v1 + r2.y);
                } else {
                    *(float2*)(C + rbase + c) = make_float2(v0, v1);
                }
            }
        }
    }
}

// ---------------------------------------------------------------------------
// Tensor-core causal flash attention (tf32 mma).
// Q tile 64 per CTA (4 warps x m16), KV tile 64, dh=64.
// ---------------------------------------------------------------------------
#define PITCH 72
#define ATT_SMEM (3 * 64 * PITCH * 4)

__global__ void __launch_bounds__(128) attn_tc_kernel(
    const float* __restrict__ qkv, float* __restrict__ out)
{
    extern __shared__ float sm[];
    float* Ks = sm;
    float* Vs = sm + 64 * PITCH;
    float* Ps = sm + 2 * 64 * PITCH;

    int tid = threadIdx.x;
    int wid = tid >> 5, lane = tid & 31;
    int gID = lane >> 2, tig = lane & 3;
    int b = blockIdx.y >> 4, h = blockIdx.y & 15;
    int q0 = blockIdx.x * 64;
    const float scale = 0.125f;

    #pragma unroll
    for (int i = 0; i < 8; i++) {
        int f = tid + i * 128;
        int r = f >> 4;
        int c = (f & 15) * 4;
        float4 v = *(const float4*)&qkv[(size_t)(b * SS + q0 + r) * (3 * DD) + h * DHH + c];
        uint32_t* dst = (uint32_t*)&Ps[r * PITCH + c];
        dst[0] = f2tf32(v.x * scale); dst[1] = f2tf32(v.y * scale);
        dst[2] = f2tf32(v.z * scale); dst[3] = f2tf32(v.w * scale);
    }
    __syncthreads();

    int rA = wid * 16 + gID;
    uint32_t qf[8][4];
    #pragma unroll
    for (int s = 0; s < 8; s++) {
        qf[s][0] = __float_as_uint(Ps[rA * PITCH + 8 * s + tig]);
        qf[s][1] = __float_as_uint(Ps[(rA + 8) * PITCH + 8 * s + tig]);
        qf[s][2] = __float_as_uint(Ps[rA * PITCH + 8 * s + tig + 4]);
        qf[s][3] = __float_as_uint(Ps[(rA + 8) * PITCH + 8 * s + tig + 4]);
    }

    float of[8][4];
    #pragma unroll
    for (int ni = 0; ni < 8; ni++)
        #pragma unroll
        for (int j = 0; j < 4; j++) of[ni][j] = 0.f;
    float m0 = -1e30f, m1 = -1e30f, l0 = 0.f, l1 = 0.f;

    int nt = blockIdx.x + 1;
    for (int jt = 0; jt < nt; jt++) {
        int k0 = jt * 64;
        __syncthreads();
        #pragma unroll
        for (int i = 0; i < 8; i++) {
            int f = tid + i * 128;
            int r = f >> 4;
            int c = (f & 15) * 4;
            size_t gb = (size_t)(b * SS + k0 + r) * (3 * DD) + h * DHH + c;
            float4 kv = *(const float4*)&qkv[gb + DD];
            float4 vv = *(const float4*)&qkv[gb + 2 * DD];
            uint32_t* dk = (uint32_t*)&Ks[r * PITCH + c];
            dk[0] = f2tf32(kv.x); dk[1] = f2tf32(kv.y); dk[2] = f2tf32(kv.z); dk[3] = f2tf32(kv.w);
            uint32_t* dv = (uint32_t*)&Vs[r * PITCH + c];
            dv[0] = f2tf32(vv.x); dv[1] = f2tf32(vv.y); dv[2] = f2tf32(vv.z); dv[3] = f2tf32(vv.w);
        }
        __syncthreads();

        float sc[8][4];
        #pragma unroll
        for (int ni = 0; ni < 8; ni++)
            #pragma unroll
            for (int j = 0; j < 4; j++) sc[ni][j] = 0.f;
        #pragma unroll
        for (int s = 0; s < 8; s++) {
            #pragma unroll
            for (int ni = 0; ni < 8; ni++) {
                uint32_t b0 = __float_as_uint(Ks[(ni * 8 + gID) * PITCH + 8 * s + tig]);
                uint32_t b1 = __float_as_uint(Ks[(ni * 8 + gID) * PITCH + 8 * s + tig + 4]);
                mma_tf32(sc[ni], qf[s], b0, b1);
            }
        }

        if (jt == nt - 1) {
            #pragma unroll
            for (int ni = 0; ni < 8; ni++) {
                int ct = ni * 8 + 2 * tig;
                if (ct > rA)         sc[ni][0] = -1e30f;
                if (ct + 1 > rA)     sc[ni][1] = -1e30f;
                if (ct > rA + 8)     sc[ni][2] = -1e30f;
                if (ct + 1 > rA + 8) sc[ni][3] = -1e30f;
            }
        }

        float mx0 = -1e30f, mx1 = -1e30f;
        #pragma unroll
        for (int ni = 0; ni < 8; ni++) {
            mx0 = fmaxf(mx0, fmaxf(sc[ni][0], sc[ni][1]));
            mx1 = fmaxf(mx1, fmaxf(sc[ni][2], sc[ni][3]));
        }
        mx0 = fmaxf(mx0, __shfl_xor_sync(0xffffffffu, mx0, 1));
        mx0 = fmaxf(mx0, __shfl_xor_sync(0xffffffffu, mx0, 2));
        mx1 = fmaxf(mx1, __shfl_xor_sync(0xffffffffu, mx1, 1));
        mx1 = fmaxf(mx1, __shfl_xor_sync(0xffffffffu, mx1, 2));
        float mn0 = fmaxf(m0, mx0), mn1 = fmaxf(m1, mx1);
        float rs0 = expf(m0 - mn0), rs1 = expf(m1 - mn1);
        m0 = mn0; m1 = mn1;

        float sum0 = 0.f, sum1 = 0.f;
        #pragma unroll
        for (int ni = 0; ni < 8; ni++) {
            sc[ni][0] = expf(sc[ni][0] - mn0);
            sc[ni][1] = expf(sc[ni][1] - mn0);
            sc[ni][2] = expf(sc[ni][2] - mn1);
            sc[ni][3] = expf(sc[ni][3] - mn1);
            sum0 += sc[ni][0] + sc[ni][1];
            sum1 += sc[ni][2] + sc[ni][3];
        }
        sum0 += __shfl_xor_sync(0xffffffffu, sum0, 1);
        sum0 += __shfl_xor_sync(0xffffffffu, sum0, 2);
        sum1 += __shfl_xor_sync(0xffffffffu, sum1, 1);
        sum1 += __shfl_xor_sync(0xffffffffu, sum1, 2);
        l0 = l0 * rs0 + sum0;
        l1 = l1 * rs1 + sum1;

        #pragma unroll
        for (int ni = 0; ni < 8; ni++) {
            of[ni][0] *= rs0; of[ni][1] *= rs0;
            of[ni][2] *= rs1; of[ni][3] *= rs1;
        }

        #pragma unroll
        for (int ni = 0; ni < 8; ni++) {
            uint32_t* p0 = (uint32_t*)&Ps[rA * PITCH + ni * 8 + 2 * tig];
            p0[0] = f2tf32(sc[ni][0]); p0[1] = f2tf32(sc[ni][1]);
            uint32_t* p1 = (uint32_t*)&Ps[(rA + 8) * PITCH + ni * 8 + 2 * tig];
            p1[0] = f2tf32(sc[ni][2]); p1[1] = f2tf32(sc[ni][3]);
        }
        __syncwarp();

        #pragma unroll
        for (int s = 0; s < 8; s++) {
            uint32_t pa[4];
            pa[0] = __float_as_uint(Ps[rA * PITCH + 8 * s + tig]);
            pa[1] = __float_as_uint(Ps[(rA + 8) * PITCH + 8 * s + tig]);
            pa[2] = __float_as_uint(Ps[rA * PITCH + 8 * s + tig + 4]);
            pa[3] = __float_as_uint(Ps[(rA + 8) * PITCH + 8 * s + tig + 4]);
            #pragma unroll
            for (int ni = 0; ni < 8; ni++) {
                uint32_t b0 = __float_as_uint(Vs[(8 * s + tig) * PITCH + ni * 8 + gID]);
                uint32_t b1 = __float_as_uint(Vs[(8 * s + tig + 4) * PITCH + ni * 8 + gID]);
                mma_tf32(of[ni], pa, b0, b1);
            }
        }
        __syncwarp();
    }

    float inv0 = 1.0f / l0, inv1 = 1.0f / l1;
    size_t row0 = (size_t)(b * SS + q0 + rA);
    #pragma unroll
    for (int ni = 0; ni < 8; ni++) {
        int d = h * DHH + ni * 8 + 2 * tig;
        *(float2*)&out[row0 * DD + d]       = make_float2(of[ni][0] * inv0, of[ni][1] * inv0);
        *(float2*)&out[(row0 + 8) * DD + d] = make_float2(of[ni][2] * inv1, of[ni][3] * inv1);
    }
}

// ---------------------------------------------------------------------------
// LayerNorm: one block per row (D=1024, 256 threads, 4 floats/thread)
// ---------------------------------------------------------------------------
__global__ void __launch_bounds__(256) ln_kernel(
    const float* __restrict__ x, const float* __restrict__ w,
    const float* __restrict__ b, float* __restrict__ out)
{
    int row = blockIdx.x;
    int tid = threadIdx.x;
    const float4* xr = (const float4*)(x + (size_t)row * DD);
    float4 v = xr[tid];

    __shared__ float red[8];
    float s = v.x + v.y + v.z + v.w;
    #pragma unroll
    for (int o = 16; o > 0; o >>= 1) s += __shfl_xor_sync(0xffffffffu, s, o);
    if ((tid & 31) == 0) red[tid >> 5] = s;
    __syncthreads();
    __shared__ float s_mean, s_rstd;
    if (tid == 0) {
        float t = 0.f;
        #pragma unroll
        for (int i = 0; i < 8; i++) t += red[i];
        s_mean = t * (1.0f / DD);
    }
    __syncthreads();
    float mean = s_mean;
    float d0 = v.x - mean, d1 = v.y - mean, d2 = v.z - mean, d3 = v.w - mean;
    float sq = d0*d0 + d1*d1 + d2*d2 + d3*d3;
    #pragma unroll
    for (int o = 16; o > 0; o >>= 1) sq += __shfl_xor_sync(0xffffffffu, sq, o);
    __syncthreads();
    if ((tid & 31) == 0) red[tid >> 5] = sq;
    __syncthreads();
    if (tid == 0) {
        float t = 0.f;
        #pragma unroll
        for (int i = 0; i < 8; i++) t += red[i];
        s_rstd = rsqrtf(t * (1.0f / DD) + 1e-5f);
    }
    __syncthreads();
    float rstd = s_rstd;
    float4 wv = ((const float4*)w)[tid];
    float4 bv = ((const float4*)b)[tid];
    float4 o4;
    o4.x = d0 * rstd * wv.x + bv.x;
    o4.y = d1 * rstd * wv.y + bv.y;
    o4.z = d2 * rstd * wv.z + bv.z;
    o4.w = d3 * rstd * wv.w + bv.w;
    ((float4*)(out + (size_t)row * DD))[tid] = o4;
}

// ---------------------------------------------------------------------------
// INL integrator: elementwise, 5 unrolled steps (DT=0.1, TARGET=0)
// ---------------------------------------------------------------------------
__global__ void __launch_bounds__(256) integrate_kernel(
    const float* __restrict__ xs0, const float* __restrict__ u,
    const float* __restrict__ al, const float* __restrict__ be,
    const float* __restrict__ gg, const float* __restrict__ x1,
    float* __restrict__ x2)
{
    int i = blockIdx.x * blockDim.x + threadIdx.x;
    float4 xs = ((const float4*)xs0)[i];
    float4 uu = ((const float4*)u)[i];
    float4 aa = ((const float4*)al)[i];
    float4 bb = ((const float4*)be)[i];
    float4 g4 = ((const float4*)gg)[i];
    float4 r1 = ((const float4*)x1)[i];
    float4 vs = make_float4(0.f, 0.f, 0.f, 0.f);
    const float DT = 0.1f;
    #pragma unroll
    for (int t = 0; t < 5; t++) {
        vs.x += DT * (-aa.x * xs.x - bb.x * vs.x + uu.x);  xs.x += DT * g4.x * vs.x;
        vs.y += DT * (-aa.y * xs.y - bb.y * vs.y + uu.y);  xs.y += DT * g4.y * vs.y;
        vs.z += DT * (-aa.z * xs.z - bb.z * vs.z + uu.z);  xs.z += DT * g4.z * vs.z;
        vs.w += DT * (-aa.w * xs.w - bb.w * vs.w + uu.w);  xs.w += DT * g4.w * vs.w;
    }
    float4 o4 = make_float4(r1.x + xs.x, r1.y + xs.y, r1.z + xs.z, r1.w + xs.w);
    ((float4*)x2)[i] = o4;
}

// ---------------------------------------------------------------------------
// Host launcher
// ---------------------------------------------------------------------------
extern "C" void kernel_launch(void* const* d_in, const int* in_sizes, int n_in,
                              void* d_out, int out_size)
{
    const float* x          = (const float*)d_in[0];
    const float* ln_attn_w  = (const float*)d_in[1];
    const float* ln_attn_b  = (const float*)d_in[2];
    const float* attn_in_w  = (const float*)d_in[3];
    const float* attn_in_b  = (const float*)d_in[4];
    const float* attn_out_w = (const float*)d_in[5];
    const float* attn_out_b = (const float*)d_in[6];
    const float* ln1_w      = (const float*)d_in[7];
    const float* ln1_b      = (const float*)d_in[8];
    const float* ln2_w      = (const float*)d_in[9];
    const float* ln2_b      = (const float*)d_in[10];
    const float* inl_u_w    = (const float*)d_in[11];
    const float* inl_u_b    = (const float*)d_in[12];
    const float* inl_a_w    = (const float*)d_in[13];
    const float* inl_a_b    = (const float*)d_in[14];
    const float* inl_b_w    = (const float*)d_in[15];
    const float* inl_b_b    = (const float*)d_in[16];
    const float* inl_g_w    = (const float*)d_in[17];
    const float* inl_g_b    = (const float*)d_in[18];
    const float* ff1_w      = (const float*)d_in[19];
    const float* ff1_b      = (const float*)d_in[20];
    const float* ff2_w      = (const float*)d_in[21];
    const float* ff2_b      = (const float*)d_in[22];
    float* out = (float*)d_out;

    float *p_ln, *p_qkv, *p_att, *p_ctx, *p_x1, *p_xs, *p_u, *p_al, *p_be, *p_gg, *p_x2, *p_ff;
    cudaGetSymbolAddress((void**)&p_ln,  g_ln);
    cudaGetSymbolAddress((void**)&p_qkv, g_qkv);
    cudaGetSymbolAddress((void**)&p_att, g_att);
    cudaGetSymbolAddress((void**)&p_ctx, g_ctx);
    cudaGetSymbolAddress((void**)&p_x1,  g_x1);
    cudaGetSymbolAddress((void**)&p_xs,  g_xs);
    cudaGetSymbolAddress((void**)&p_u,   g_u);
    cudaGetSymbolAddress((void**)&p_al,  g_al);
    cudaGetSymbolAddress((void**)&p_be,  g_be);
    cudaGetSymbolAddress((void**)&p_gg,  g_gg);
    cudaGetSymbolAddress((void**)&p_x2,  g_x2);
    cudaGetSymbolAddress((void**)&p_ff,  g_ff);

    cudaFuncSetAttribute(gemm_tc<0>, cudaFuncAttributeMaxDynamicSharedMemorySize, GEMM_SMEM);
    cudaFuncSetAttribute(gemm_tc<1>, cudaFuncAttributeMaxDynamicSharedMemorySize, GEMM_SMEM);
    cudaFuncSetAttribute(gemm_tc<2>, cudaFuncAttributeMaxDynamicSharedMemorySize, GEMM_SMEM);
    cudaFuncSetAttribute(gemm_tc<3>, cudaFuncAttributeMaxDynamicSharedMemorySize, GEMM_SMEM);
    cudaFuncSetAttribute(gemm_tc<4>, cudaFuncAttributeMaxDynamicSharedMemorySize, GEMM_SMEM);
    cudaFuncSetAttribute(gemm_tc<5>, cudaFuncAttributeMaxDynamicSharedMemorySize, GEMM_SMEM);
    cudaFuncSetAttribute(attn_tc_kernel, cudaFuncAttributeMaxDynamicSharedMemorySize, ATT_SMEM);

    // 1. ln_attn(x) -> g_ln
    ln_kernel<<<MM, 256>>>(x, ln_attn_w, ln_attn_b, p_ln);
    // 2. qkv = g_ln @ attn_in_w^T + b   [8192,3072]
    gemm_tc<0><<<dim3(3 * DD / 128, MM / 128), 128, GEMM_SMEM>>>(
        p_ln, attn_in_w, attn_in_b, p_qkv, nullptr, nullptr, MM, 3 * DD, DD);
    // 3. causal MHA (tensor core) -> g_att
    attn_tc_kernel<<<dim3(SS / 64, BB * HH), 128, ATT_SMEM>>>(p_qkv, p_att);
    // 4. ctx = g_att @ attn_out_w^T + b ; x1 = x + ctx
    gemm_tc<5><<<dim3(DD / 128, MM / 128), 128, GEMM_SMEM>>>(
        p_att, attn_out_w, attn_out_b, p_ctx, p_x1, x, MM, DD, DD);
    // 5. xs = ln1(x1)
    ln_kernel<<<MM, 256>>>(p_x1, ln1_w, ln1_b, p_xs);
    // 6. INL controllers from ctx
    gemm_tc<0><<<dim3(DD / 128, MM / 128), 128, GEMM_SMEM>>>(
        p_ctx, inl_u_w, inl_u_b, p_u, nullptr, nullptr, MM, DD, DD);
    gemm_tc<2><<<dim3(DD / 128, MM / 128), 128, GEMM_SMEM>>>(
        p_ctx, inl_a_w, inl_a_b, p_al, nullptr, nullptr, MM, DD, DD);
    gemm_tc<3><<<dim3(DD / 128, MM / 128), 128, GEMM_SMEM>>>(
        p_ctx, inl_b_w, inl_b_b, p_be, nullptr, nullptr, MM, DD, DD);
    gemm_tc<2><<<dim3(DD / 128, MM / 128), 128, GEMM_SMEM>>>(
        p_ctx, inl_g_w, inl_g_b, p_gg, nullptr, nullptr, MM, DD, DD);
    // 7. integrate -> x2 = x1 + xs_final
    integrate_kernel<<<(MM * DD / 4) / 256, 256>>>(p_xs, p_u, p_al, p_be, p_gg, p_x1, p_x2);
    // 8. ln2(x2) -> g_ln
    ln_kernel<<<MM, 256>>>(p_x2, ln2_w, ln2_b, p_ln);
    // 9. ff1 + exact GELU -> g_ff   [8192,4096]
    gemm_tc<1><<<dim3(FFD / 128, MM / 128), 128, GEMM_SMEM>>>(
        p_ln, ff1_w, ff1_b, p_ff, nullptr, nullptr, MM, FFD, DD);
    // 10. out = g_ff @ ff2_w^T + b + x2
    gemm_tc<4><<<dim3(DD / 128, MM / 128), 128, GEMM_SMEM>>>(
        p_ff, ff2_w, ff2_b, out, nullptr, p_x2, MM, DD, FFD);
}

// round 7
// speedup vs baseline: 4.5495x; 1.2464x over previous
#include <cuda_runtime.h>
#include <cstdint>
#include <math.h>

// Problem constants
#define BB   4
#define SS   2048
#define DD   1024
#define HH   16
#define DHH  64
#define FFD  4096
#define MM   (BB*SS)      // 8192 rows

// ---------------------------------------------------------------------------
// Scratch (static __device__ — no allocations allowed)
// ---------------------------------------------------------------------------
__device__ float g_ln [MM*DD];       // tf32 (GEMM A input)
__device__ float g_qkv[MM*3*DD];     // fp32 (attention input)
__device__ float g_att[MM*DD];       // tf32 (GEMM A input)
__device__ float g_ctx[MM*DD];       // tf32 (GEMM A input)
__device__ float g_x1 [MM*DD];       // fp32
__device__ float g_xs [MM*DD];       // fp32
__device__ float g_u  [MM*DD];
__device__ float g_al [MM*DD];
__device__ float g_be [MM*DD];
__device__ float g_gg [MM*DD];
__device__ float g_x2 [MM*DD];
__device__ float g_ff [MM*FFD];      // tf32 (GEMM A input)
// Pre-converted tf32 weights
__device__ float g_w_qkv[3*DD*DD];
__device__ float g_w_out[DD*DD];
__device__ float g_w_u [DD*DD];
__device__ float g_w_a [DD*DD];
__device__ float g_w_b [DD*DD];
__device__ float g_w_g [DD*DD];
__device__ float g_w_f1[FFD*DD];
__device__ float g_w_f2[DD*FFD];

// ---------------------------------------------------------------------------
// Helpers
// ---------------------------------------------------------------------------
__device__ __forceinline__ uint32_t smem_u32(const void* p) {
    uint32_t a;
    asm("{ .reg .u64 t; cvta.to.shared.u64 t, %1; cvt.u32.u64 %0, t; }" : "=r"(a) : "l"(p));
    return a;
}
__device__ __forceinline__ uint32_t f2tf32(float f) {
    uint32_t u;
    asm("cvt.rna.tf32.f32 %0, %1;" : "=r"(u) : "f"(f));
    return u;
}
__device__ __forceinline__ uint32_t lds_u32(uint32_t addr) {
    uint32_t v;
    asm volatile("ld.shared.b32 %0, [%1];" : "=r"(v) : "r"(addr));
    return v;
}
__device__ __forceinline__ void cp16(uint32_t dst, const float* src) {
    asm volatile("cp.async.cg.shared.global [%0], [%1], 16;" :: "r"(dst), "l"(src));
}
#define CP_COMMIT() asm volatile("cp.async.commit_group;" ::: "memory")
__device__ __forceinline__ void cp_wait1() { asm volatile("cp.async.wait_group 1;" ::: "memory"); }
__device__ __forceinline__ void cp_wait0() { asm volatile("cp.async.wait_group 0;" ::: "memory"); }
#define SWZ128(off) ((off) ^ (((off) >> 3) & 0x70))

__device__ __forceinline__ void mma_tf32(float* c, const uint32_t* a, uint32_t b0, uint32_t b1) {
    asm volatile("mma.sync.aligned.m16n8k8.row.col.f32.tf32.tf32.f32 "
        "{%0,%1,%2,%3}, {%4,%5,%6,%7}, {%8,%9}, {%0,%1,%2,%3};"
        : "+f"(c[0]), "+f"(c[1]), "+f"(c[2]), "+f"(c[3])
        : "r"(a[0]), "r"(a[1]), "r"(a[2]), "r"(a[3]), "r"(b0), "r"(b1));
}

// ---------------------------------------------------------------------------
// Weight/tensor tf32 pre-rounding kernel
// ---------------------------------------------------------------------------
__global__ void __launch_bounds__(256) cvt_tf32_kernel(
    const float* __restrict__ src, float* __restrict__ dst)
{
    int i = blockIdx.x * blockDim.x + threadIdx.x;
    float4 v = ((const float4*)src)[i];
    uint4 o = make_uint4(f2tf32(v.x), f2tf32(v.y), f2tf32(v.z), f2tf32(v.w));
    ((uint4*)dst)[i] = o;
}

// ---------------------------------------------------------------------------
// tf32 tensor GEMM: C[M,N] = A[M,K] @ W[N,K]^T + bias (+ epilogue)
// A and W must be pre-rounded tf32 values stored as float.
// CTA tile 128x128, 128 threads = 4 warps (2M x 2N), warp tile 64x64.
// K-chunk 32, 3-stage cp.async pipeline (3 x 32KB smem), one barrier/chunk.
// Fragment double-buffering across the 4 k8-steps.
// EPI: 0=none 1=gelu 2=sigmoid 3=softplus 4=C=v+res 5=dual(C=v, C2=v+res)
// CT32: round C store to tf32 (when C feeds another GEMM as A).
// ---------------------------------------------------------------------------
#define STAGE_BYTES 32768   // A tile 16KB + B tile 16KB
#define NSTAGE 3
#define GEMM_SMEM   (NSTAGE * STAGE_BYTES + 1024)

template<int EPI, bool CT32>
__global__ void __launch_bounds__(128, 2) gemm_tc(
    const float* __restrict__ A, const float* __restrict__ W,
    const float* __restrict__ bias, float* __restrict__ C,
    float* __restrict__ C2, const float* __restrict__ res,
    int M, int N, int K)
{
    extern __shared__ char dsm[];
    uint32_t raw = smem_u32(dsm);
    uint32_t base = (raw + 1023u) & ~1023u;

    int tid = threadIdx.x;
    int wid = tid >> 5, lane = tid & 31;
    int gID = lane >> 2, tig = lane & 3;
    int wm = (wid & 1) * 64;
    int wn = (wid >> 1) * 64;

    // cp.async map: thread covers rows (tid>>3)+16i, 16B col chunk (tid&7)
    const uint32_t gOff0 = (uint32_t)((tid >> 3) * K + (tid & 7) * 4);
    const uint32_t gStep = (uint32_t)(16 * K);
    const uint32_t sOff0 = SWZ128((uint32_t)((tid >> 3) * 128 + (tid & 7) * 16));

    const float* Abase = A + (size_t)(blockIdx.y * 128) * K;
    const float* Wbase = W + (size_t)(blockIdx.x * 128) * K;

    const uint32_t rowA0 = (uint32_t)((wm + gID) * 128);
    const uint32_t rowB0 = (uint32_t)((wn + gID) * 128);
    const uint32_t xmask = (uint32_t)(gID << 4);

    float acc[4][8][4];
    #pragma unroll
    for (int mi = 0; mi < 4; mi++)
        #pragma unroll
        for (int ni = 0; ni < 8; ni++)
            #pragma unroll
            for (int j = 0; j < 4; j++) acc[mi][ni][j] = 0.f;

    const int niter = K / 32;

    // Prologue: stage chunks 0 and 1
    #pragma unroll
    for (int p = 0; p < 2; p++) {
        uint32_t st = base + p * STAGE_BYTES;
        const float* As = Abase + p * 32;
        const float* Ws = Wbase + p * 32;
        #pragma unroll
        for (int i = 0; i < 8; i++) cp16(st + sOff0 + i * 2048, As + gOff0 + i * gStep);
        #pragma unroll
        for (int i = 0; i < 8; i++) cp16(st + 16384 + sOff0 + i * 2048, Ws + gOff0 + i * gStep);
        CP_COMMIT();
    }

    int stage = 0;
    for (int it = 0; it < niter; it++) {
        if (it + 1 < niter) cp_wait1(); else cp_wait0();
        __syncthreads();

        if (it + 2 < niter) {
            int ns = stage + 2; if (ns >= NSTAGE) ns -= NSTAGE;
            uint32_t st = base + ns * STAGE_BYTES;
            const float* As = Abase + (it + 2) * 32;
            const float* Ws = Wbase + (it + 2) * 32;
            #pragma unroll
            for (int i = 0; i < 8; i++) cp16(st + sOff0 + i * 2048, As + gOff0 + i * gStep);
            #pragma unroll
            for (int i = 0; i < 8; i++) cp16(st + 16384 + sOff0 + i * 2048, Ws + gOff0 + i * gStep);
            CP_COMMIT();
        }

        uint32_t sA = base + stage * STAGE_BYTES;
        uint32_t sB = sA + 16384;

        // Fragment double-buffered 4 k8-steps
        uint32_t af[2][4][4];
        uint32_t bf[2][8][2];
        {
            uint32_t x0 = ((uint32_t)(tig * 4)) ^ xmask;
            uint32_t x1 = x0 ^ 16u;
            #pragma unroll
            for (int mi = 0; mi < 4; mi++) {
                af[0][mi][0] = lds_u32(sA + rowA0 + mi * 2048 + x0);
                af[0][mi][1] = lds_u32(sA + rowA0 + mi * 2048 + 1024 + x0);
                af[0][mi][2] = lds_u32(sA + rowA0 + mi * 2048 + x1);
                af[0][mi][3] = lds_u32(sA + rowA0 + mi * 2048 + 1024 + x1);
            }
            #pragma unroll
            for (int ni = 0; ni < 8; ni++) {
                bf[0][ni][0] = lds_u32(sB + rowB0 + ni * 1024 + x0);
                bf[0][ni][1] = lds_u32(sB + rowB0 + ni * 1024 + x1);
            }
        }
        #pragma unroll
        for (int s = 0; s < 4; s++) {
            int cur = s & 1, nxt = cur ^ 1;
            if (s < 3) {
                uint32_t x0 = ((uint32_t)((s + 1) * 32 + tig * 4)) ^ xmask;
                uint32_t x1 = x0 ^ 16u;
                #pragma unroll
                for (int mi = 0; mi < 4; mi++) {
                    af[nxt][mi][0] = lds_u32(sA + rowA0 + mi * 2048 + x0);
                    af[nxt][mi][1] = lds_u32(sA + rowA0 + mi * 2048 + 1024 + x0);
                    af[nxt][mi][2] = lds_u32(sA + rowA0 + mi * 2048 + x1);
                    af[nxt][mi][3] = lds_u32(sA + rowA0 + mi * 2048 + 1024 + x1);
                }
                #pragma unroll
                for (int ni = 0; ni < 8; ni++) {
                    bf[nxt][ni][0] = lds_u32(sB + rowB0 + ni * 1024 + x0);
                    bf[nxt][ni][1] = lds_u32(sB + rowB0 + ni * 1024 + x1);
                }
            }
            #pragma unroll
            for (int ni = 0; ni < 8; ni++)
                #pragma unroll
                for (int mi = 0; mi < 4; mi++)
                    mma_tf32(acc[mi][ni], af[cur][mi], bf[cur][ni][0], bf[cur][ni][1]);
        }

        stage++; if (stage >= NSTAGE) stage = 0;
    }

    // Epilogue
    int row0 = blockIdx.y * 128 + wm + gID;
    int col0 = blockIdx.x * 128 + wn;
    #pragma unroll
    for (int mi = 0; mi < 4; mi++) {
        #pragma unroll
        for (int half = 0; half < 2; half++) {
            int r = row0 + mi * 16 + half * 8;
            size_t rbase = (size_t)r * N;
            #pragma unroll
            for (int ni = 0; ni < 8; ni++) {
                int c = col0 + ni * 8 + 2 * tig;
                float v0 = acc[mi][ni][half * 2 + 0] + bias[c];
                float v1 = acc[mi][ni][half * 2 + 1] + bias[c + 1];
                if (EPI == 1) {
                    v0 = 0.5f * v0 * (1.0f + erff(v0 * 0.70710678118654752f));
                    v1 = 0.5f * v1 * (1.0f + erff(v1 * 0.70710678118654752f));
                } else if (EPI == 2) {
                    v0 = 1.0f / (1.0f + expf(-v0));
                    v1 = 1.0f / (1.0f + expf(-v1));
                } else if (EPI == 3) {
                    v0 = (v0 > 0.f) ? (v0 + log1pf(expf(-v0))) : log1pf(expf(v0));
                    v1 = (v1 > 0.f) ? (v1 + log1pf(expf(-v1))) : log1pf(expf(v1));
                }
                float c0 = CT32 ? __uint_as_float(f2tf32(v0)) : v0;
                float c1 = CT32 ? __uint_as_float(f2tf32(v1)) : v1;
                if (EPI == 4) {
                    float2 r2 = *(const float2*)(res + rbase + c);
                    *(float2*)(C + rbase + c) = make_float2(v0 + r2.x, v1 + r2.y);
                } else if (EPI == 5) {
                    float2 r2 = *(const float2*)(res + rbase + c);
                    *(float2*)(C + rbase + c)  = make_float2(c0, c1);
                    *(float2*)(C2 + rbase + c) = make_float2(v0 + r2.x, v1 + r2.y);
                } else {
                    *(float2*)(C + rbase + c) = make_float2(c0, c1);
                }
            }
        }
    }
}

// ---------------------------------------------------------------------------
// Tensor-core causal flash attention (tf32 mma). Output stored tf32 (feeds GEMM).
// ---------------------------------------------------------------------------
#define PITCH 72
#define ATT_SMEM (3 * 64 * PITCH * 4)

__global__ void __launch_bounds__(128) attn_tc_kernel(
    const float* __restrict__ qkv, float* __restrict__ out)
{
    extern __shared__ float sm[];
    float* Ks = sm;
    float* Vs = sm + 64 * PITCH;
    float* Ps = sm + 2 * 64 * PITCH;

    int tid = threadIdx.x;
    int wid = tid >> 5, lane = tid & 31;
    int gID = lane >> 2, tig = lane & 3;
    int b = blockIdx.y >> 4, h = blockIdx.y & 15;
    int q0 = blockIdx.x * 64;
    const float scale = 0.125f;

    #pragma unroll
    for (int i = 0; i < 8; i++) {
        int f = tid + i * 128;
        int r = f >> 4;
        int c = (f & 15) * 4;
        float4 v = *(const float4*)&qkv[(size_t)(b * SS + q0 + r) * (3 * DD) + h * DHH + c];
        uint32_t* dst = (uint32_t*)&Ps[r * PITCH + c];
        dst[0] = f2tf32(v.x * scale); dst[1] = f2tf32(v.y * scale);
        dst[2] = f2tf32(v.z * scale); dst[3] = f2tf32(v.w * scale);
    }
    __syncthreads();

    int rA = wid * 16 + gID;
    uint32_t qf[8][4];
    #pragma unroll
    for (int s = 0; s < 8; s++) {
        qf[s][0] = __float_as_uint(Ps[rA * PITCH + 8 * s + tig]);
        qf[s][1] = __float_as_uint(Ps[(rA + 8) * PITCH + 8 * s + tig]);
        qf[s][2] = __float_as_uint(Ps[rA * PITCH + 8 * s + tig + 4]);
        qf[s][3] = __float_as_uint(Ps[(rA + 8) * PITCH + 8 * s + tig + 4]);
    }

    float of[8][4];
    #pragma unroll
    for (int ni = 0; ni < 8; ni++)
        #pragma unroll
        for (int j = 0; j < 4; j++) of[ni][j] = 0.f;
    float m0 = -1e30f, m1 = -1e30f, l0 = 0.f, l1 = 0.f;

    int nt = blockIdx.x + 1;
    for (int jt = 0; jt < nt; jt++) {
        int k0 = jt * 64;
        __syncthreads();
        #pragma unroll
        for (int i = 0; i < 8; i++) {
            int f = tid + i * 128;
            int r = f >> 4;
            int c = (f & 15) * 4;
            size_t gb = (size_t)(b * SS + k0 + r) * (3 * DD) + h * DHH + c;
            float4 kv = *(const float4*)&qkv[gb + DD];
            float4 vv = *(const float4*)&qkv[gb + 2 * DD];
            uint32_t* dk = (uint32_t*)&Ks[r * PITCH + c];
            dk[0] = f2tf32(kv.x); dk[1] = f2tf32(kv.y); dk[2] = f2tf32(kv.z); dk[3] = f2tf32(kv.w);
            uint32_t* dv = (uint32_t*)&Vs[r * PITCH + c];
            dv[0] = f2tf32(vv.x); dv[1] = f2tf32(vv.y); dv[2] = f2tf32(vv.z); dv[3] = f2tf32(vv.w);
        }
        __syncthreads();

        float sc[8][4];
        #pragma unroll
        for (int ni = 0; ni < 8; ni++)
            #pragma unroll
            for (int j = 0; j < 4; j++) sc[ni][j] = 0.f;
        #pragma unroll
        for (int s = 0; s < 8; s++) {
            #pragma unroll
            for (int ni = 0; ni < 8; ni++) {
                uint32_t b0 = __float_as_uint(Ks[(ni * 8 + gID) * PITCH + 8 * s + tig]);
                uint32_t b1 = __float_as_uint(Ks[(ni * 8 + gID) * PITCH + 8 * s + tig + 4]);
                mma_tf32(sc[ni], qf[s], b0, b1);
            }
        }

        if (jt == nt - 1) {
            #pragma unroll
            for (int ni = 0; ni < 8; ni++) {
                int ct = ni * 8 + 2 * tig;
                if (ct > rA)         sc[ni][0] = -1e30f;
                if (ct + 1 > rA)     sc[ni][1] = -1e30f;
                if (ct > rA + 8)     sc[ni][2] = -1e30f;
                if (ct + 1 > rA + 8) sc[ni][3] = -1e30f;
            }
        }

        float mx0 = -1e30f, mx1 = -1e30f;
        #pragma unroll
        for (int ni = 0; ni < 8; ni++) {
            mx0 = fmaxf(mx0, fmaxf(sc[ni][0], sc[ni][1]));
            mx1 = fmaxf(mx1, fmaxf(sc[ni][2], sc[ni][3]));
        }
        mx0 = fmaxf(mx0, __shfl_xor_sync(0xffffffffu, mx0, 1));
        mx0 = fmaxf(mx0, __shfl_xor_sync(0xffffffffu, mx0, 2));
        mx1 = fmaxf(mx1, __shfl_xor_sync(0xffffffffu, mx1, 1));
        mx1 = fmaxf(mx1, __shfl_xor_sync(0xffffffffu, mx1, 2));
        float mn0 = fmaxf(m0, mx0), mn1 = fmaxf(m1, mx1);
        float rs0 = expf(m0 - mn0), rs1 = expf(m1 - mn1);
        m0 = mn0; m1 = mn1;

        float sum0 = 0.f, sum1 = 0.f;
        #pragma unroll
        for (int ni = 0; ni < 8; ni++) {
            sc[ni][0] = expf(sc[ni][0] - mn0);
            sc[ni][1] = expf(sc[ni][1] - mn0);
            sc[ni][2] = expf(sc[ni][2] - mn1);
            sc[ni][3] = expf(sc[ni][3] - mn1);
            sum0 += sc[ni][0] + sc[ni][1];
            sum1 += sc[ni][2] + sc[ni][3];
        }
        sum0 += __shfl_xor_sync(0xffffffffu, sum0, 1);
        sum0 += __shfl_xor_sync(0xffffffffu, sum0, 2);
        sum1 += __shfl_xor_sync(0xffffffffu, sum1, 1);
        sum1 += __shfl_xor_sync(0xffffffffu, sum1, 2);
        l0 = l0 * rs0 + sum0;
        l1 = l1 * rs1 + sum1;

        #pragma unroll
        for (int ni = 0; ni < 8; ni++) {
            of[ni][0] *= rs0; of[ni][1] *= rs0;
            of[ni][2] *= rs1; of[ni][3] *= rs1;
        }

        #pragma unroll
        for (int ni = 0; ni < 8; ni++) {
            uint32_t* p0 = (uint32_t*)&Ps[rA * PITCH + ni * 8 + 2 * tig];
            p0[0] = f2tf32(sc[ni][0]); p0[1] = f2tf32(sc[ni][1]);
            uint32_t* p1 = (uint32_t*)&Ps[(rA + 8) * PITCH + ni * 8 + 2 * tig];
            p1[0] = f2tf32(sc[ni][2]); p1[1] = f2tf32(sc[ni][3]);
        }
        __syncwarp();

        #pragma unroll
        for (int s = 0; s < 8; s++) {
            uint32_t pa[4];
            pa[0] = __float_as_uint(Ps[rA * PITCH + 8 * s + tig]);
            pa[1] = __float_as_uint(Ps[(rA + 8) * PITCH + 8 * s + tig]);
            pa[2] = __float_as_uint(Ps[rA * PITCH + 8 * s + tig + 4]);
            pa[3] = __float_as_uint(Ps[(rA + 8) * PITCH + 8 * s + tig + 4]);
            #pragma unroll
            for (int ni = 0; ni < 8; ni++) {
                uint32_t b0 = __float_as_uint(Vs[(8 * s + tig) * PITCH + ni * 8 + gID]);
                uint32_t b1 = __float_as_uint(Vs[(8 * s + tig + 4) * PITCH + ni * 8 + gID]);
                mma_tf32(of[ni], pa, b0, b1);
            }
        }
        __syncwarp();
    }

    float inv0 = 1.0f / l0, inv1 = 1.0f / l1;
    size_t row0 = (size_t)(b * SS + q0 + rA);
    #pragma unroll
    for (int ni = 0; ni < 8; ni++) {
        int d = h * DHH + ni * 8 + 2 * tig;
        uint2 o0 = make_uint2(f2tf32(of[ni][0] * inv0), f2tf32(of[ni][1] * inv0));
        uint2 o1 = make_uint2(f2tf32(of[ni][2] * inv1), f2tf32(of[ni][3] * inv1));
        *(uint2*)&out[row0 * DD + d]       = o0;
        *(uint2*)&out[(row0 + 8) * DD + d] = o1;
    }
}

// ---------------------------------------------------------------------------
// LayerNorm: one block per row. TF32OUT rounds output (when it feeds a GEMM).
// ---------------------------------------------------------------------------
template<bool TF32OUT>
__global__ void __launch_bounds__(256) ln_kernel(
    const float* __restrict__ x, const float* __restrict__ w,
    const float* __restrict__ b, float* __restrict__ out)
{
    int row = blockIdx.x;
    int tid = threadIdx.x;
    const float4* xr = (const float4*)(x + (size_t)row * DD);
    float4 v = xr[tid];

    __shared__ float red[8];
    float s = v.x + v.y + v.z + v.w;
    #pragma unroll
    for (int o = 16; o > 0; o >>= 1) s += __shfl_xor_sync(0xffffffffu, s, o);
    if ((tid & 31) == 0) red[tid >> 5] = s;
    __syncthreads();
    __shared__ float s_mean, s_rstd;
    if (tid == 0) {
        float t = 0.f;
        #pragma unroll
        for (int i = 0; i < 8; i++) t += red[i];
        s_mean = t * (1.0f / DD);
    }
    __syncthreads();
    float mean = s_mean;
    float d0 = v.x - mean, d1 = v.y - mean, d2 = v.z - mean, d3 = v.w - mean;
    float sq = d0*d0 + d1*d1 + d2*d2 + d3*d3;
    #pragma unroll
    for (int o = 16; o > 0; o >>= 1) sq += __shfl_xor_sync(0xffffffffu, sq, o);
    __syncthreads();
    if ((tid & 31) == 0) red[tid >> 5] = sq;
    __syncthreads();
    if (tid == 0) {
        float t = 0.f;
        #pragma unroll
        for (int i = 0; i < 8; i++) t += red[i];
        s_rstd = rsqrtf(t * (1.0f / DD) + 1e-5f);
    }
    __syncthreads();
    float rstd = s_rstd;
    float4 wv = ((const float4*)w)[tid];
    float4 bv = ((const float4*)b)[tid];
    float o0 = d0 * rstd * wv.x + bv.x;
    float o1 = d1 * rstd * wv.y + bv.y;
    float o2 = d2 * rstd * wv.z + bv.z;
    float o3 = d3 * rstd * wv.w + bv.w;
    if (TF32OUT) {
        uint4 o4 = make_uint4(f2tf32(o0), f2tf32(o1), f2tf32(o2), f2tf32(o3));
        ((uint4*)(out + (size_t)row * DD))[tid] = o4;
    } else {
        ((float4*)(out + (size_t)row * DD))[tid] = make_float4(o0, o1, o2, o3);
    }
}

// ---------------------------------------------------------------------------
// INL integrator: elementwise, 5 unrolled steps (DT=0.1, TARGET=0)
// ---------------------------------------------------------------------------
__global__ void __launch_bounds__(256) integrate_kernel(
    const float* __restrict__ xs0, const float* __restrict__ u,
    const float* __restrict__ al, const float* __restrict__ be,
    const float* __restrict__ gg, const float* __restrict__ x1,
    float* __restrict__ x2)
{
    int i = blockIdx.x * blockDim.x + threadIdx.x;
    float4 xs = ((const float4*)xs0)[i];
    float4 uu = ((const float4*)u)[i];
    float4 aa = ((const float4*)al)[i];
    float4 bb = ((const float4*)be)[i];
    float4 g4 = ((const float4*)gg)[i];
    float4 r1 = ((const float4*)x1)[i];
    float4 vs = make_float4(0.f, 0.f, 0.f, 0.f);
    const float DT = 0.1f;
    #pragma unroll
    for (int t = 0; t < 5; t++) {
        vs.x += DT * (-aa.x * xs.x - bb.x * vs.x + uu.x);  xs.x += DT * g4.x * vs.x;
        vs.y += DT * (-aa.y * xs.y - bb.y * vs.y + uu.y);  xs.y += DT * g4.y * vs.y;
        vs.z += DT * (-aa.z * xs.z - bb.z * vs.z + uu.z);  xs.z += DT * g4.z * vs.z;
        vs.w += DT * (-aa.w * xs.w - bb.w * vs.w + uu.w);  xs.w += DT * g4.w * vs.w;
    }
    float4 o4 = make_float4(r1.x + xs.x, r1.y + xs.y, r1.z + xs.z, r1.w + xs.w);
    ((float4*)x2)[i] = o4;
}

// ---------------------------------------------------------------------------
// Host launcher
// ---------------------------------------------------------------------------
extern "C" void kernel_launch(void* const* d_in, const int* in_sizes, int n_in,
                              void* d_out, int out_size)
{
    const float* x          = (const float*)d_in[0];
    const float* ln_attn_w  = (const float*)d_in[1];
    const float* ln_attn_b  = (const float*)d_in[2];
    const float* attn_in_w  = (const float*)d_in[3];
    const float* attn_in_b  = (const float*)d_in[4];
    const float* attn_out_w = (const float*)d_in[5];
    const float* attn_out_b = (const float*)d_in[6];
    const float* ln1_w      = (const float*)d_in[7];
    const float* ln1_b      = (const float*)d_in[8];
    const float* ln2_w      = (const float*)d_in[9];
    const float* ln2_b      = (const float*)d_in[10];
    const float* inl_u_w    = (const float*)d_in[11];
    const float* inl_u_b    = (const float*)d_in[12];
    const float* inl_a_w    = (const float*)d_in[13];
    const float* inl_a_b    = (const float*)d_in[14];
    const float* inl_b_w    = (const float*)d_in[15];
    const float* inl_b_b    = (const float*)d_in[16];
    const float* inl_g_w    = (const float*)d_in[17];
    const float* inl_g_b    = (const float*)d_in[18];
    const float* ff1_w      = (const float*)d_in[19];
    const float* ff1_b      = (const float*)d_in[20];
    const float* ff2_w      = (const float*)d_in[21];
    const float* ff2_b      = (const float*)d_in[22];
    float* out = (float*)d_out;

    float *p_ln, *p_qkv, *p_att, *p_ctx, *p_x1, *p_xs, *p_u, *p_al, *p_be, *p_gg, *p_x2, *p_ff;
    float *w_qkv, *w_out, *w_u, *w_a, *w_b, *w_g, *w_f1, *w_f2;
    cudaGetSymbolAddress((void**)&p_ln,  g_ln);
    cudaGetSymbolAddress((void**)&p_qkv, g_qkv);
    cudaGetSymbolAddress((void**)&p_att, g_att);
    cudaGetSymbolAddress((void**)&p_ctx, g_ctx);
    cudaGetSymbolAddress((void**)&p_x1,  g_x1);
    cudaGetSymbolAddress((void**)&p_xs,  g_xs);
    cudaGetSymbolAddress((void**)&p_u,   g_u);
    cudaGetSymbolAddress((void**)&p_al,  g_al);
    cudaGetSymbolAddress((void**)&p_be,  g_be);
    cudaGetSymbolAddress((void**)&p_gg,  g_gg);
    cudaGetSymbolAddress((void**)&p_x2,  g_x2);
    cudaGetSymbolAddress((void**)&p_ff,  g_ff);
    cudaGetSymbolAddress((void**)&w_qkv, g_w_qkv);
    cudaGetSymbolAddress((void**)&w_out, g_w_out);
    cudaGetSymbolAddress((void**)&w_u,   g_w_u);
    cudaGetSymbolAddress((void**)&w_a,   g_w_a);
    cudaGetSymbolAddress((void**)&w_b,   g_w_b);
    cudaGetSymbolAddress((void**)&w_g,   g_w_g);
    cudaGetSymbolAddress((void**)&w_f1,  g_w_f1);
    cudaGetSymbolAddress((void**)&w_f2,  g_w_f2);

    cudaFuncSetAttribute((const void*)gemm_tc<0,false>, cudaFuncAttributeMaxDynamicSharedMemorySize, GEMM_SMEM);
    cudaFuncSetAttribute((const void*)gemm_tc<1,true>,  cudaFuncAttributeMaxDynamicSharedMemorySize, GEMM_SMEM);
    cudaFuncSetAttribute((const void*)gemm_tc<2,false>, cudaFuncAttributeMaxDynamicSharedMemorySize, GEMM_SMEM);
    cudaFuncSetAttribute((const void*)gemm_tc<3,false>, cudaFuncAttributeMaxDynamicSharedMemorySize, GEMM_SMEM);
    cudaFuncSetAttribute((const void*)gemm_tc<4,false>, cudaFuncAttributeMaxDynamicSharedMemorySize, GEMM_SMEM);
    cudaFuncSetAttribute((const void*)gemm_tc<5,true>,  cudaFuncAttributeMaxDynamicSharedMemorySize, GEMM_SMEM);
    cudaFuncSetAttribute((const void*)attn_tc_kernel,   cudaFuncAttributeMaxDynamicSharedMemorySize, ATT_SMEM);

    // 0. Pre-round weights to tf32
    cvt_tf32_kernel<<<3 * DD * DD / 1024, 256>>>(attn_in_w, w_qkv);
    cvt_tf32_kernel<<<DD * DD / 1024, 256>>>(attn_out_w, w_out);
    cvt_tf32_kernel<<<DD * DD / 1024, 256>>>(inl_u_w, w_u);
    cvt_tf32_kernel<<<DD * DD / 1024, 256>>>(inl_a_w, w_a);
    cvt_tf32_kernel<<<DD * DD / 1024, 256>>>(inl_b_w, w_b);
    cvt_tf32_kernel<<<DD * DD / 1024, 256>>>(inl_g_w, w_g);
    cvt_tf32_kernel<<<FFD * DD / 1024, 256>>>(ff1_w, w_f1);
    cvt_tf32_kernel<<<DD * FFD / 1024, 256>>>(ff2_w, w_f2);

    // 1. ln_attn(x) -> g_ln (tf32)
    ln_kernel<true><<<MM, 256>>>(x, ln_attn_w, ln_attn_b, p_ln);
    // 2. qkv = g_ln @ w_qkv^T + b  (fp32 out, feeds attention)
    gemm_tc<0,false><<<dim3(3 * DD / 128, MM / 128), 128, GEMM_SMEM>>>(
        p_ln, w_qkv, attn_in_b, p_qkv, nullptr, nullptr, MM, 3 * DD, DD);
    // 3. causal MHA -> g_att (tf32)
    attn_tc_kernel<<<dim3(SS / 64, BB * HH), 128, ATT_SMEM>>>(p_qkv, p_att);
    // 4. ctx(tf32) = g_att @ w_out^T + b ; x1(fp32) = x + ctx
    gemm_tc<5,true><<<dim3(DD / 128, MM / 128), 128, GEMM_SMEM>>>(
        p_att, w_out, attn_out_b, p_ctx, p_x1, x, MM, DD, DD);
    // 5. xs = ln1(x1) (fp32, integrator input)
    ln_kernel<false><<<MM, 256>>>(p_x1, ln1_w, ln1_b, p_xs);
    // 6. INL controllers from ctx
    gemm_tc<0,false><<<dim3(DD / 128, MM / 128), 128, GEMM_SMEM>>>(
        p_ctx, w_u, inl_u_b, p_u, nullptr, nullptr, MM, DD, DD);
    gemm_tc<2,false><<<dim3(DD / 128, MM / 128), 128, GEMM_SMEM>>>(
        p_ctx, w_a, inl_a_b, p_al, nullptr, nullptr, MM, DD, DD);
    gemm_tc<3,false><<<dim3(DD / 128, MM / 128), 128, GEMM_SMEM>>>(
        p_ctx, w_b, inl_b_b, p_be, nullptr, nullptr, MM, DD, DD);
    gemm_tc<2,false><<<dim3(DD / 128, MM / 128), 128, GEMM_SMEM>>>(
        p_ctx, w_g, inl_g_b, p_gg, nullptr, nullptr, MM, DD, DD);
    // 7. integrate -> x2 = x1 + xs_final
    integrate_kernel<<<(MM * DD / 4) / 256, 256>>>(p_xs, p_u, p_al, p_be, p_gg, p_x1, p_x2);
    // 8. ln2(x2) -> g_ln (tf32)
    ln_kernel<true><<<MM, 256>>>(p_x2, ln2_w, ln2_b, p_ln);
    // 9. ff1 + exact GELU -> g_ff (tf32)
    gemm_tc<1,true><<<dim3(FFD / 128, MM / 128), 128, GEMM_SMEM>>>(
        p_ln, w_f1, ff1_b, p_ff, nullptr, nullptr, MM, FFD, DD);
    // 10. out = g_ff @ w_f2^T + b + x2
    gemm_tc<4,false><<<dim3(DD / 128, MM / 128), 128, GEMM_SMEM>>>(
        p_ff, w_f2, ff2_b, out, nullptr, p_x2, MM, DD, FFD);
}

// round 9
// speedup vs baseline: 6.7946x; 1.4935x over previous
#include <cuda_runtime.h>
#include <cuda_bf16.h>
#include <cstdint>
#include <math.h>

// Problem constants
#define BB   4
#define SS   2048
#define DD   1024
#define HH   16
#define DHH  64
#define FFD  4096
#define MM   (BB*SS)      // 8192 rows

typedef __nv_bfloat16 bf16;

// ---------------------------------------------------------------------------
// Scratch (static __device__ — no allocations allowed)
// ---------------------------------------------------------------------------
__device__ bf16  g_ln [MM*DD];       // bf16 (GEMM A input)
__device__ float g_qkv[MM*3*DD];     // fp32 (attention input)
__device__ bf16  g_att[MM*DD];       // bf16 (GEMM A input)
__device__ bf16  g_ctx[MM*DD];       // bf16 (GEMM A input)
__device__ float g_x1 [MM*DD];
__device__ float g_xs [MM*DD];
__device__ float g_u  [MM*DD];
__device__ float g_al [MM*DD];
__device__ float g_be [MM*DD];
__device__ float g_gg [MM*DD];
__device__ float g_x2 [MM*DD];
__device__ bf16  g_ff [MM*FFD];      // bf16 (GEMM A input)
// Pre-converted bf16 weights
__device__ bf16 g_w_qkv[3*DD*DD];
__device__ bf16 g_w_out[DD*DD];
__device__ bf16 g_w_u [DD*DD];
__device__ bf16 g_w_a [DD*DD];
__device__ bf16 g_w_b [DD*DD];
__device__ bf16 g_w_g [DD*DD];
__device__ bf16 g_w_f1[FFD*DD];
__device__ bf16 g_w_f2[DD*FFD];

// ---------------------------------------------------------------------------
// Helpers
// ---------------------------------------------------------------------------
__device__ __forceinline__ uint32_t smem_u32(const void* p) {
    uint32_t a;
    asm("{ .reg .u64 t; cvta.to.shared.u64 t, %1; cvt.u32.u64 %0, t; }" : "=r"(a) : "l"(p));
    return a;
}
__device__ __forceinline__ uint32_t f2tf32(float f) {
    uint32_t u;
    asm("cvt.rna.tf32.f32 %0, %1;" : "=r"(u) : "f"(f));
    return u;
}
__device__ __forceinline__ uint32_t pack_bf2(float lo, float hi) {
    __nv_bfloat162 h = __floats2bfloat162_rn(lo, hi);
    return *reinterpret_cast<uint32_t*>(&h);
}
__device__ __forceinline__ uint32_t lds_u32(uint32_t addr) {
    uint32_t v;
    asm volatile("ld.shared.b32 %0, [%1];" : "=r"(v) : "r"(addr));
    return v;
}
__device__ __forceinline__ void cp16(uint32_t dst, const void* src) {
    asm volatile("cp.async.cg.shared.global [%0], [%1], 16;" :: "r"(dst), "l"(src));
}
#define CP_COMMIT() asm volatile("cp.async.commit_group;" ::: "memory")
__device__ __forceinline__ void cp_wait1() { asm volatile("cp.async.wait_group 1;" ::: "memory"); }
__device__ __forceinline__ void cp_wait0() { asm volatile("cp.async.wait_group 0;" ::: "memory"); }
#define SWZ128(off) ((off) ^ (((off) >> 3) & 0x70))

__device__ __forceinline__ void mma_bf16(float* c, const uint32_t* a, uint32_t b0, uint32_t b1) {
    asm volatile("mma.sync.aligned.m16n8k16.row.col.f32.bf16.bf16.f32 "
        "{%0,%1,%2,%3}, {%4,%5,%6,%7}, {%8,%9}, {%0,%1,%2,%3};"
        : "+f"(c[0]), "+f"(c[1]), "+f"(c[2]), "+f"(c[3])
        : "r"(a[0]), "r"(a[1]), "r"(a[2]), "r"(a[3]), "r"(b0), "r"(b1));
}
__device__ __forceinline__ void mma_tf32(float* c, const uint32_t* a, uint32_t b0, uint32_t b1) {
    asm volatile("mma.sync.aligned.m16n8k8.row.col.f32.tf32.tf32.f32 "
        "{%0,%1,%2,%3}, {%4,%5,%6,%7}, {%8,%9}, {%0,%1,%2,%3};"
        : "+f"(c[0]), "+f"(c[1]), "+f"(c[2]), "+f"(c[3])
        : "r"(a[0]), "r"(a[1]), "r"(a[2]), "r"(a[3]), "r"(b0), "r"(b1));
}

// ---------------------------------------------------------------------------
// fp32 -> bf16 weight conversion: 8 elements per thread
// ---------------------------------------------------------------------------
__global__ void __launch_bounds__(256) cvt_bf16_kernel(
    const float* __restrict__ src, bf16* __restrict__ dst)
{
    int i = blockIdx.x * blockDim.x + threadIdx.x;
    float4 v0 = ((const float4*)src)[2 * i];
    float4 v1 = ((const float4*)src)[2 * i + 1];
    uint4 o;
    o.x = pack_bf2(v0.x, v0.y);
    o.y = pack_bf2(v0.z, v0.w);
    o.z = pack_bf2(v1.x, v1.y);
    o.w = pack_bf2(v1.z, v1.w);
    ((uint4*)dst)[i] = o;
}

// ---------------------------------------------------------------------------
// bf16 tensor GEMM: C[M,N] = A[M,K] @ W[N,K]^T + bias (+ epilogue)
// A, W are bf16. CTA tile 128x128, 128 threads = 4 warps (2Mx2N), warp 64x64.
// K-chunk 64 (128B rows, SW128), 3-stage cp.async, m16n8k16 bf16 mma,
// fragment double-buffering across the 4 k16-steps.
// EPI: 0=none 1=gelu 2=sigmoid 3=softplus 4=C=v+res 5=dual(C=v, C2=v+res)
// CB16: C stored as bf16 (feeds another GEMM); else fp32.
// ---------------------------------------------------------------------------
#define STAGE_BYTES 32768   // A tile 16KB + B tile 16KB (128 rows x 128B)
#define NSTAGE 3
#define GEMM_SMEM   (NSTAGE * STAGE_BYTES + 1024)

template<int EPI, bool CB16>
__global__ void __launch_bounds__(128, 2) gemm_tc(
    const bf16* __restrict__ A, const bf16* __restrict__ W,
    const float* __restrict__ bias, void* __restrict__ Cv,
    float* __restrict__ C2, const float* __restrict__ res,
    int M, int N, int K)
{
    extern __shared__ char dsm[];
    uint32_t raw = smem_u32(dsm);
    uint32_t base = (raw + 1023u) & ~1023u;

    int tid = threadIdx.x;
    int wid = tid >> 5, lane = tid & 31;
    int gID = lane >> 2, tig = lane & 3;
    int wm = (wid & 1) * 64;
    int wn = (wid >> 1) * 64;

    // cp.async map: thread covers rows (tid>>3)+16i, 16B chunk (tid&7) (= 8 bf16)
    const uint32_t gOff0 = (uint32_t)((tid >> 3) * K + (tid & 7) * 8);
    const uint32_t gStep = (uint32_t)(16 * K);
    const uint32_t sOff0 = SWZ128((uint32_t)((tid >> 3) * 128 + (tid & 7) * 16));

    const bf16* Abase = A + (size_t)(blockIdx.y * 128) * K;
    const bf16* Wbase = W + (size_t)(blockIdx.x * 128) * K;

    const uint32_t rowA0 = (uint32_t)((wm + gID) * 128);
    const uint32_t rowB0 = (uint32_t)((wn + gID) * 128);
    const uint32_t xmask = (uint32_t)(gID << 4);

    float acc[4][8][4];
    #pragma unroll
    for (int mi = 0; mi < 4; mi++)
        #pragma unroll
        for (int ni = 0; ni < 8; ni++)
            #pragma unroll
            for (int j = 0; j < 4; j++) acc[mi][ni][j] = 0.f;

    const int niter = K / 64;

    // Prologue: stage chunks 0 and 1
    #pragma unroll
    for (int p = 0; p < 2; p++) {
        uint32_t st = base + p * STAGE_BYTES;
        const bf16* As = Abase + p * 64;
        const bf16* Ws = Wbase + p * 64;
        #pragma unroll
        for (int i = 0; i < 8; i++) cp16(st + sOff0 + i * 2048, As + gOff0 + i * gStep);
        #pragma unroll
        for (int i = 0; i < 8; i++) cp16(st + 16384 + sOff0 + i * 2048, Ws + gOff0 + i * gStep);
        CP_COMMIT();
    }

    int stage = 0;
    for (int it = 0; it < niter; it++) {
        if (it + 1 < niter) cp_wait1(); else cp_wait0();
        __syncthreads();

        if (it + 2 < niter) {
            int ns = stage + 2; if (ns >= NSTAGE) ns -= NSTAGE;
            uint32_t st = base + ns * STAGE_BYTES;
            const bf16* As = Abase + (it + 2) * 64;
            const bf16* Ws = Wbase + (it + 2) * 64;
            #pragma unroll
            for (int i = 0; i < 8; i++) cp16(st + sOff0 + i * 2048, As + gOff0 + i * gStep);
            #pragma unroll
            for (int i = 0; i < 8; i++) cp16(st + 16384 + sOff0 + i * 2048, Ws + gOff0 + i * gStep);
            CP_COMMIT();
        }

        uint32_t sA = base + stage * STAGE_BYTES;
        uint32_t sB = sA + 16384;

        // 4 k16-steps, fragment double-buffered. Byte layout identical to the
        // tf32 version: step s covers bytes [s*32, s*32+32) of each 128B row.
        uint32_t af[2][4][4];
        uint32_t bf[2][8][2];
        {
            uint32_t x0 = ((uint32_t)(tig * 4)) ^ xmask;
            uint32_t x1 = x0 ^ 16u;
            #pragma unroll
            for (int mi = 0; mi < 4; mi++) {
                af[0][mi][0] = lds_u32(sA + rowA0 + mi * 2048 + x0);
                af[0][mi][1] = lds_u32(sA + rowA0 + mi * 2048 + 1024 + x0);
                af[0][mi][2] = lds_u32(sA + rowA0 + mi * 2048 + x1);
                af[0][mi][3] = lds_u32(sA + rowA0 + mi * 2048 + 1024 + x1);
            }
            #pragma unroll
            for (int ni = 0; ni < 8; ni++) {
                bf[0][ni][0] = lds_u32(sB + rowB0 + ni * 1024 + x0);
                bf[0][ni][1] = lds_u32(sB + rowB0 + ni * 1024 + x1);
            }
        }
        #pragma unroll
        for (int s = 0; s < 4; s++) {
            int cur = s & 1, nxt = cur ^ 1;
            if (s < 3) {
                uint32_t x0 = ((uint32_t)((s + 1) * 32 + tig * 4)) ^ xmask;
                uint32_t x1 = x0 ^ 16u;
                #pragma unroll
                for (int mi = 0; mi < 4; mi++) {
                    af[nxt][mi][0] = lds_u32(sA + rowA0 + mi * 2048 + x0);
                    af[nxt][mi][1] = lds_u32(sA + rowA0 + mi * 2048 + 1024 + x0);
                    af[nxt][mi][2] = lds_u32(sA + rowA0 + mi * 2048 + x1);
                    af[nxt][mi][3] = lds_u32(sA + rowA0 + mi * 2048 + 1024 + x1);
                }
                #pragma unroll
                for (int ni = 0; ni < 8; ni++) {
                    bf[nxt][ni][0] = lds_u32(sB + rowB0 + ni * 1024 + x0);
                    bf[nxt][ni][1] = lds_u32(sB + rowB0 + ni * 1024 + x1);
                }
            }
            #pragma unroll
            for (int ni = 0; ni < 8; ni++)
                #pragma unroll
                for (int mi = 0; mi < 4; mi++)
                    mma_bf16(acc[mi][ni], af[cur][mi], bf[cur][ni][0], bf[cur][ni][1]);
        }

        stage++; if (stage >= NSTAGE) stage = 0;
    }

    // Epilogue
    float* Cf = (float*)Cv;
    bf16*  Cb = (bf16*)Cv;
    int row0 = blockIdx.y * 128 + wm + gID;
    int col0 = blockIdx.x * 128 + wn;
    #pragma unroll
    for (int mi = 0; mi < 4; mi++) {
        #pragma unroll
        for (int half = 0; half < 2; half++) {
            int r = row0 + mi * 16 + half * 8;
            size_t rbase = (size_t)r * N;
            #pragma unroll
            for (int ni = 0; ni < 8; ni++) {
                int c = col0 + ni * 8 + 2 * tig;
                float v0 = acc[mi][ni][half * 2 + 0] + bias[c];
                float v1 = acc[mi][ni][half * 2 + 1] + bias[c + 1];
                if (EPI == 1) {
                    v0 = 0.5f * v0 * (1.0f + erff(v0 * 0.70710678118654752f));
                    v1 = 0.5f * v1 * (1.0f + erff(v1 * 0.70710678118654752f));
                } else if (EPI == 2) {
                    v0 = 1.0f / (1.0f + expf(-v0));
                    v1 = 1.0f / (1.0f + expf(-v1));
                } else if (EPI == 3) {
                    v0 = (v0 > 0.f) ? (v0 + log1pf(expf(-v0))) : log1pf(expf(v0));
                    v1 = (v1 > 0.f) ? (v1 + log1pf(expf(-v1))) : log1pf(expf(v1));
                }
                if (EPI == 4) {
                    float2 r2 = *(const float2*)(res + rbase + c);
                    *(float2*)(Cf + rbase + c) = make_float2(v0 + r2.x, v1 + r2.y);
                } else if (EPI == 5) {
                    float2 r2 = *(const float2*)(res + rbase + c);
                    *(uint32_t*)(Cb + rbase + c) = pack_bf2(v0, v1);
                    *(float2*)(C2 + rbase + c) = make_float2(v0 + r2.x, v1 + r2.y);
                } else if (CB16) {
                    *(uint32_t*)(Cb + rbase + c) = pack_bf2(v0, v1);
                } else {
                    *(float2*)(Cf + rbase + c) = make_float2(v0, v1);
                }
            }
        }
    }
}

// ---------------------------------------------------------------------------
// Tensor-core causal flash attention (tf32 mma internally; bf16 output).
// ---------------------------------------------------------------------------
#define PITCH 72
#define ATT_SMEM (3 * 64 * PITCH * 4)

__global__ void __launch_bounds__(128) attn_tc_kernel(
    const float* __restrict__ qkv, bf16* __restrict__ out)
{
    extern __shared__ float sm[];
    float* Ks = sm;
    float* Vs = sm + 64 * PITCH;
    float* Ps = sm + 2 * 64 * PITCH;

    int tid = threadIdx.x;
    int wid = tid >> 5, lane = tid & 31;
    int gID = lane >> 2, tig = lane & 3;
    int b = blockIdx.y >> 4, h = blockIdx.y & 15;
    int q0 = blockIdx.x * 64;
    const float scale = 0.125f;

    #pragma unroll
    for (int i = 0; i < 8; i++) {
        int f = tid + i * 128;
        int r = f >> 4;
        int c = (f & 15) * 4;
        float4 v = *(const float4*)&qkv[(size_t)(b * SS + q0 + r) * (3 * DD) + h * DHH + c];
        uint32_t* dst = (uint32_t*)&Ps[r * PITCH + c];
        dst[0] = f2tf32(v.x * scale); dst[1] = f2tf32(v.y * scale);
        dst[2] = f2tf32(v.z * scale); dst[3] = f2tf32(v.w * scale);
    }
    __syncthreads();

    int rA = wid * 16 + gID;
    uint32_t qf[8][4];
    #pragma unroll
    for (int s = 0; s < 8; s++) {
        qf[s][0] = __float_as_uint(Ps[rA * PITCH + 8 * s + tig]);
        qf[s][1] = __float_as_uint(Ps[(rA + 8) * PITCH + 8 * s + tig]);
        qf[s][2] = __float_as_uint(Ps[rA * PITCH + 8 * s + tig + 4]);
        qf[s][3] = __float_as_uint(Ps[(rA + 8) * PITCH + 8 * s + tig + 4]);
    }

    float of[8][4];
    #pragma unroll
    for (int ni = 0; ni < 8; ni++)
        #pragma unroll
        for (int j = 0; j < 4; j++) of[ni][j] = 0.f;
    float m0 = -1e30f, m1 = -1e30f, l0 = 0.f, l1 = 0.f;

    int nt = blockIdx.x + 1;
    for (int jt = 0; jt < nt; jt++) {
        int k0 = jt * 64;
        __syncthreads();
        #pragma unroll
        for (int i = 0; i < 8; i++) {
            int f = tid + i * 128;
            int r = f >> 4;
            int c = (f & 15) * 4;
            size_t gb = (size_t)(b * SS + k0 + r) * (3 * DD) + h * DHH + c;
            float4 kv = *(const float4*)&qkv[gb + DD];
            float4 vv = *(const float4*)&qkv[gb + 2 * DD];
            uint32_t* dk = (uint32_t*)&Ks[r * PITCH + c];
            dk[0] = f2tf32(kv.x); dk[1] = f2tf32(kv.y); dk[2] = f2tf32(kv.z); dk[3] = f2tf32(kv.w);
            uint32_t* dv = (uint32_t*)&Vs[r * PITCH + c];
            dv[0] = f2tf32(vv.x); dv[1] = f2tf32(vv.y); dv[2] = f2tf32(vv.z); dv[3] = f2tf32(vv.w);
        }
        __syncthreads();

        float sc[8][4];
        #pragma unroll
        for (int ni = 0; ni < 8; ni++)
            #pragma unroll
            for (int j = 0; j < 4; j++) sc[ni][j] = 0.f;
        #pragma unroll
        for (int s = 0; s < 8; s++) {
            #pragma unroll
            for (int ni = 0; ni < 8; ni++) {
                uint32_t b0 = __float_as_uint(Ks[(ni * 8 + gID) * PITCH + 8 * s + tig]);
                uint32_t b1 = __float_as_uint(Ks[(ni * 8 + gID) * PITCH + 8 * s + tig + 4]);
                mma_tf32(sc[ni], qf[s], b0, b1);
            }
        }

        if (jt == nt - 1) {
            #pragma unroll
            for (int ni = 0; ni < 8; ni++) {
                int ct = ni * 8 + 2 * tig;
                if (ct > rA)         sc[ni][0] = -1e30f;
                if (ct + 1 > rA)     sc[ni][1] = -1e30f;
                if (ct > rA + 8)     sc[ni][2] = -1e30f;
                if (ct + 1 > rA + 8) sc[ni][3] = -1e30f;
            }
        }

        float mx0 = -1e30f, mx1 = -1e30f;
        #pragma unroll
        for (int ni = 0; ni < 8; ni++) {
            mx0 = fmaxf(mx0, fmaxf(sc[ni][0], sc[ni][1]));
            mx1 = fmaxf(mx1, fmaxf(sc[ni][2], sc[ni][3]));
        }
        mx0 = fmaxf(mx0, __shfl_xor_sync(0xffffffffu, mx0, 1));
        mx0 = fmaxf(mx0, __shfl_xor_sync(0xffffffffu, mx0, 2));
        mx1 = fmaxf(mx1, __shfl_xor_sync(0xffffffffu, mx1, 1));
        mx1 = fmaxf(mx1, __shfl_xor_sync(0xffffffffu, mx1, 2));
        float mn0 = fmaxf(m0, mx0), mn1 = fmaxf(m1, mx1);
        float rs0 = expf(m0 - mn0), rs1 = expf(m1 - mn1);
        m0 = mn0; m1 = mn1;

        float sum0 = 0.f, sum1 = 0.f;
        #pragma unroll
        for (int ni = 0; ni < 8; ni++) {
            sc[ni][0] = expf(sc[ni][0] - mn0);
            sc[ni][1] = expf(sc[ni][1] - mn0);
            sc[ni][2] = expf(sc[ni][2] - mn1);
            sc[ni][3] = expf(sc[ni][3] - mn1);
            sum0 += sc[ni][0] + sc[ni][1];
            sum1 += sc[ni][2] + sc[ni][3];
        }
        sum0 += __shfl_xor_sync(0xffffffffu, sum0, 1);
        sum0 += __shfl_xor_sync(0xffffffffu, sum0, 2);
        sum1 += __shfl_xor_sync(0xffffffffu, sum1, 1);
        sum1 += __shfl_xor_sync(0xffffffffu, sum1, 2);
        l0 = l0 * rs0 + sum0;
        l1 = l1 * rs1 + sum1;

        #pragma unroll
        for (int ni = 0; ni < 8; ni++) {
            of[ni][0] *= rs0; of[ni][1] *= rs0;
            of[ni][2] *= rs1; of[ni][3] *= rs1;
        }

        #pragma unroll
        for (int ni = 0; ni < 8; ni++) {
            uint32_t* p0 = (uint32_t*)&Ps[rA * PITCH + ni * 8 + 2 * tig];
            p0[0] = f2tf32(sc[ni][0]); p0[1] = f2tf32(sc[ni][1]);
            uint32_t* p1 = (uint32_t*)&Ps[(rA + 8) * PITCH + ni * 8 + 2 * tig];
            p1[0] = f2tf32(sc[ni][2]); p1[1] = f2tf32(sc[ni][3]);
        }
        __syncwarp();

        #pragma unroll
        for (int s = 0; s < 8; s++) {
            uint32_t pa[4];
            pa[0] = __float_as_uint(Ps[rA * PITCH + 8 * s + tig]);
            pa[1] = __float_as_uint(Ps[(rA + 8) * PITCH + 8 * s + tig]);
            pa[2] = __float_as_uint(Ps[rA * PITCH + 8 * s + tig + 4]);
            pa[3] = __float_as_uint(Ps[(rA + 8) * PITCH + 8 * s + tig + 4]);
            #pragma unroll
            for (int ni = 0; ni < 8; ni++) {
                uint32_t b0 = __float_as_uint(Vs[(8 * s + tig) * PITCH + ni * 8 + gID]);
                uint32_t b1 = __float_as_uint(Vs[(8 * s + tig + 4) * PITCH + ni * 8 + gID]);
                mma_tf32(of[ni], pa, b0, b1);
            }
        }
        __syncwarp();
    }

    float inv0 = 1.0f / l0, inv1 = 1.0f / l1;
    size_t row0 = (size_t)(b * SS + q0 + rA);
    #pragma unroll
    for (int ni = 0; ni < 8; ni++) {
        int d = h * DHH + ni * 8 + 2 * tig;
        *(uint32_t*)&out[row0 * DD + d]       = pack_bf2(of[ni][0] * inv0, of[ni][1] * inv0);
        *(uint32_t*)&out[(row0 + 8) * DD + d] = pack_bf2(of[ni][2] * inv1, of[ni][3] * inv1);
    }
}

// ---------------------------------------------------------------------------
// LayerNorm: one block per row. BF16OUT when the output feeds a GEMM.
// ---------------------------------------------------------------------------
template<bool BF16OUT>
__global__ void __launch_bounds__(256) ln_kernel(
    const float* __restrict__ x, const float* __restrict__ w,
    const float* __restrict__ b, void* __restrict__ outv)
{
    int row = blockIdx.x;
    int tid = threadIdx.x;
    const float4* xr = (const float4*)(x + (size_t)row * DD);
    float4 v = xr[tid];

    __shared__ float red[8];
    float s = v.x + v.y + v.z + v.w;
    #pragma unroll
    for (int o = 16; o > 0; o >>= 1) s += __shfl_xor_sync(0xffffffffu, s, o);
    if ((tid & 31) == 0) red[tid >> 5] = s;
    __syncthreads();
    __shared__ float s_mean, s_rstd;
    if (tid == 0) {
        float t = 0.f;
        #pragma unroll
        for (int i = 0; i < 8; i++) t += red[i];
        s_mean = t * (1.0f / DD);
    }
    __syncthreads();
    float mean = s_mean;
    float d0 = v.x - mean, d1 = v.y - mean, d2 = v.z - mean, d3 = v.w - mean;
    float sq = d0*d0 + d1*d1 + d2*d2 + d3*d3;
    #pragma unroll
    for (int o = 16; o > 0; o >>= 1) sq += __shfl_xor_sync(0xffffffffu, sq, o);
    __syncthreads();
    if ((tid & 31) == 0) red[tid >> 5] = sq;
    __syncthreads();
    if (tid == 0) {
        float t = 0.f;
        #pragma unroll
        for (int i = 0; i < 8; i++) t += red[i];
        s_rstd = rsqrtf(t * (1.0f / DD) + 1e-5f);
    }
    __syncthreads();
    float rstd = s_rstd;
    float4 wv = ((const float4*)w)[tid];
    float4 bv = ((const float4*)b)[tid];
    float o0 = d0 * rstd * wv.x + bv.x;
    float o1 = d1 * rstd * wv.y + bv.y;
    float o2 = d2 * rstd * wv.z + bv.z;
    float o3 = d3 * rstd * wv.w + bv.w;
    if (BF16OUT) {
        bf16* out = (bf16*)outv;
        uint2 o4 = make_uint2(pack_bf2(o0, o1), pack_bf2(o2, o3));
        *(uint2*)(out + (size_t)row * DD + tid * 4) = o4;
    } else {
        float* out = (float*)outv;
        ((float4*)(out + (size_t)row * DD))[tid] = make_float4(o0, o1, o2, o3);
    }
}

// ---------------------------------------------------------------------------
// INL integrator: elementwise, 5 unrolled steps (DT=0.1, TARGET=0)
// ---------------------------------------------------------------------------
__global__ void __launch_bounds__(256) integrate_kernel(
    const float* __restrict__ xs0, const float* __restrict__ u,
    const float* __restrict__ al, const float* __restrict__ be,
    const float* __restrict__ gg, const float* __restrict__ x1,
    float* __restrict__ x2)
{
    int i = blockIdx.x * blockDim.x + threadIdx.x;
    float4 xs = ((const float4*)xs0)[i];
    float4 uu = ((const float4*)u)[i];
    float4 aa = ((const float4*)al)[i];
    float4 bb = ((const float4*)be)[i];
    float4 g4 = ((const float4*)gg)[i];
    float4 r1 = ((const float4*)x1)[i];
    float4 vs = make_float4(0.f, 0.f, 0.f, 0.f);
    const float DT = 0.1f;
    #pragma unroll
    for (int t = 0; t < 5; t++) {
        vs.x += DT * (-aa.x * xs.x - bb.x * vs.x + uu.x);  xs.x += DT * g4.x * vs.x;
        vs.y += DT * (-aa.y * xs.y - bb.y * vs.y + uu.y);  xs.y += DT * g4.y * vs.y;
        vs.z += DT * (-aa.z * xs.z - bb.z * vs.z + uu.z);  xs.z += DT * g4.z * vs.z;
        vs.w += DT * (-aa.w * xs.w - bb.w * vs.w + uu.w);  xs.w += DT * g4.w * vs.w;
    }
    float4 o4 = make_float4(r1.x + xs.x, r1.y + xs.y, r1.z + xs.z, r1.w + xs.w);
    ((float4*)x2)[i] = o4;
}

// ---------------------------------------------------------------------------
// Host launcher
// ---------------------------------------------------------------------------
extern "C" void kernel_launch(void* const* d_in, const int* in_sizes, int n_in,
                              void* d_out, int out_size)
{
    const float* x          = (const float*)d_in[0];
    const float* ln_attn_w  = (const float*)d_in[1];
    const float* ln_attn_b  = (const float*)d_in[2];
    const float* attn_in_w  = (const float*)d_in[3];
    const float* attn_in_b  = (const float*)d_in[4];
    const float* attn_out_w = (const float*)d_in[5];
    const float* attn_out_b = (const float*)d_in[6];
    const float* ln1_w      = (const float*)d_in[7];
    const float* ln1_b      = (const float*)d_in[8];
    const float* ln2_w      = (const float*)d_in[9];
    const float* ln2_b      = (const float*)d_in[10];
    const float* inl_u_w    = (const float*)d_in[11];
    const float* inl_u_b    = (const float*)d_in[12];
    const float* inl_a_w    = (const float*)d_in[13];
    const float* inl_a_b    = (const float*)d_in[14];
    const float* inl_b_w    = (const float*)d_in[15];
    const float* inl_b_b    = (const float*)d_in[16];
    const float* inl_g_w    = (const float*)d_in[17];
    const float* inl_g_b    = (const float*)d_in[18];
    const float* ff1_w      = (const float*)d_in[19];
    const float* ff1_b      = (const float*)d_in[20];
    const float* ff2_w      = (const float*)d_in[21];
    const float* ff2_b      = (const float*)d_in[22];
    float* out = (float*)d_out;

    float *p_qkv, *p_x1, *p_xs, *p_u, *p_al, *p_be, *p_gg, *p_x2;
    bf16 *p_ln, *p_att, *p_ctx, *p_ff;
    bf16 *w_qkv, *w_out, *w_u, *w_a, *w_b, *w_g, *w_f1, *w_f2;
    cudaGetSymbolAddress((void**)&p_ln,  g_ln);
    cudaGetSymbolAddress((void**)&p_qkv, g_qkv);
    cudaGetSymbolAddress((void**)&p_att, g_att);
    cudaGetSymbolAddress((void**)&p_ctx, g_ctx);
    cudaGetSymbolAddress((void**)&p_x1,  g_x1);
    cudaGetSymbolAddress((void**)&p_xs,  g_xs);
    cudaGetSymbolAddress((void**)&p_u,   g_u);
    cudaGetSymbolAddress((void**)&p_al,  g_al);
    cudaGetSymbolAddress((void**)&p_be,  g_be);
    cudaGetSymbolAddress((void**)&p_gg,  g_gg);
    cudaGetSymbolAddress((void**)&p_x2,  g_x2);
    cudaGetSymbolAddress((void**)&p_ff,  g_ff);
    cudaGetSymbolAddress((void**)&w_qkv, g_w_qkv);
    cudaGetSymbolAddress((void**)&w_out, g_w_out);
    cudaGetSymbolAddress((void**)&w_u,   g_w_u);
    cudaGetSymbolAddress((void**)&w_a,   g_w_a);
    cudaGetSymbolAddress((void**)&w_b,   g_w_b);
    cudaGetSymbolAddress((void**)&w_g,   g_w_g);
    cudaGetSymbolAddress((void**)&w_f1,  g_w_f1);
    cudaGetSymbolAddress((void**)&w_f2,  g_w_f2);

    cudaFuncSetAttribute((const void*)gemm_tc<0,false>, cudaFuncAttributeMaxDynamicSharedMemorySize, GEMM_SMEM);
    cudaFuncSetAttribute((const void*)gemm_tc<1,true>,  cudaFuncAttributeMaxDynamicSharedMemorySize, GEMM_SMEM);
    cudaFuncSetAttribute((const void*)gemm_tc<2,false>, cudaFuncAttributeMaxDynamicSharedMemorySize, GEMM_SMEM);
    cudaFuncSetAttribute((const void*)gemm_tc<3,false>, cudaFuncAttributeMaxDynamicSharedMemorySize, GEMM_SMEM);
    cudaFuncSetAttribute((const void*)gemm_tc<4,false>, cudaFuncAttributeMaxDynamicSharedMemorySize, GEMM_SMEM);
    cudaFuncSetAttribute((const void*)gemm_tc<5,true>,  cudaFuncAttributeMaxDynamicSharedMemorySize, GEMM_SMEM);
    cudaFuncSetAttribute((const void*)attn_tc_kernel,   cudaFuncAttributeMaxDynamicSharedMemorySize, ATT_SMEM);

    // 0. Pre-round weights to bf16
    cvt_bf16_kernel<<<3 * DD * DD / 2048, 256>>>(attn_in_w, w_qkv);
    cvt_bf16_kernel<<<DD * DD / 2048, 256>>>(attn_out_w, w_out);
    cvt_bf16_kernel<<<DD * DD / 2048, 256>>>(inl_u_w, w_u);
    cvt_bf16_kernel<<<DD * DD / 2048, 256>>>(inl_a_w, w_a);
    cvt_bf16_kernel<<<DD * DD / 2048, 256>>>(inl_b_w, w_b);
    cvt_bf16_kernel<<<DD * DD / 2048, 256>>>(inl_g_w, w_g);
    cvt_bf16_kernel<<<FFD * DD / 2048, 256>>>(ff1_w, w_f1);
    cvt_bf16_kernel<<<DD * FFD / 2048, 256>>>(ff2_w, w_f2);

    // 1. ln_attn(x) -> g_ln (bf16)
    ln_kernel<true><<<MM, 256>>>(x, ln_attn_w, ln_attn_b, p_ln);
    // 2. qkv = g_ln @ w_qkv^T + b  (fp32 out, feeds attention)
    gemm_tc<0,false><<<dim3(3 * DD / 128, MM / 128), 128, GEMM_SMEM>>>(
        p_ln, w_qkv, attn_in_b, p_qkv, nullptr, nullptr, MM, 3 * DD, DD);
    // 3. causal MHA -> g_att (bf16)
    attn_tc_kernel<<<dim3(SS / 64, BB * HH), 128, ATT_SMEM>>>(p_qkv, p_att);
    // 4. ctx(bf16) = g_att @ w_out^T + b ; x1(fp32) = x + ctx
    gemm_tc<5,true><<<dim3(DD / 128, MM / 128), 128, GEMM_SMEM>>>(
        p_att, w_out, attn_out_b, p_ctx, p_x1, x, MM, DD, DD);
    // 5. xs = ln1(x1) (fp32, integrator input)
    ln_kernel<false><<<MM, 256>>>(p_x1, ln1_w, ln1_b, p_xs);
    // 6. INL controllers from ctx
    gemm_tc<0,false><<<dim3(DD / 128, MM / 128), 128, GEMM_SMEM>>>(
        p_ctx, w_u, inl_u_b, p_u, nullptr, nullptr, MM, DD, DD);
    gemm_tc<2,false><<<dim3(DD / 128, MM / 128), 128, GEMM_SMEM>>>(
        p_ctx, w_a, inl_a_b, p_al, nullptr, nullptr, MM, DD, DD);
    gemm_tc<3,false><<<dim3(DD / 128, MM / 128), 128, GEMM_SMEM>>>(
        p_ctx, w_b, inl_b_b, p_be, nullptr, nullptr, MM, DD, DD);
    gemm_tc<2,false><<<dim3(DD / 128, MM / 128), 128, GEMM_SMEM>>>(
        p_ctx, w_g, inl_g_b, p_gg, nullptr, nullptr, MM, DD, DD);
    // 7. integrate -> x2 = x1 + xs_final
    integrate_kernel<<<(MM * DD / 4) / 256, 256>>>(p_xs, p_u, p_al, p_be, p_gg, p_x1, p_x2);
    // 8. ln2(x2) -> g_ln (bf16)
    ln_kernel<true><<<MM, 256>>>(p_x2, ln2_w, ln2_b, p_ln);
    // 9. ff1 + exact GELU -> g_ff (bf16)
    gemm_tc<1,true><<<dim3(FFD / 128, MM / 128), 128, GEMM_SMEM>>>(
        p_ln, w_f1, ff1_b, p_ff, nullptr, nullptr, MM, FFD, DD);
    // 10. out = g_ff @ w_f2^T + b + x2
    gemm_tc<4,false><<<dim3(DD / 128, MM / 128), 128, GEMM_SMEM>>>(
        p_ff, w_f2, ff2_b, out, nullptr, p_x2, MM, DD, FFD);
}